// round 1
// baseline (speedup 1.0000x reference)
#include <cuda_runtime.h>
#include <cuda_bf16.h>

// ---------------- problem constants ----------------
#define BT   16
#define D_CH 1056
#define OH   57
#define OW   87
#define MAXN 13
#define KK   5
#define NFB  1024
#define NA   6
#define R_TOT (BT*MAXN)            // 208
#define KDIM  (D_CH*KK*KK)         // 26400
#define NPAIR_B (MAXN*(MAXN-1))    // 156
#define NPAIR   (BT*NPAIR_B)       // 2496
#define EMB_SPLITS 25              // 26400/25 = 1056 K per split (= 33 chunks of 32)

// ---------------- scratch (device globals, no allocation) ----------------
__device__ float g_roi  [R_TOT * KDIM];            // 22.0 MB
__device__ float g_part [EMB_SPLITS * R_TOT * NFB];// 21.3 MB
__device__ float g_feats[R_TOT * NFB];
__device__ float g_UV   [2 * R_TOT * NFB];

// =====================================================================
// 1) ROI align: grid (33 d-chunks, 208 rois), 256 thr (32 d-lanes x 8 p-lanes)
// =====================================================================
__global__ __launch_bounds__(256) void roi_align_kernel(
    const float* __restrict__ feat, const float* __restrict__ boxes,
    float* __restrict__ roi)
{
    int r  = blockIdx.y;
    int d0 = blockIdx.x * 32;
    int b  = r / MAXN;

    const float* bx = boxes + r * 4;
    float x1 = bx[0], y1 = bx[1], x2 = bx[2], y2 = bx[3];
    float bw = (x2 - x1) * (1.0f / KK);
    float bh = (y2 - y1) * (1.0f / KK);

    int tid = threadIdx.x;
    int dl  = tid >> 3;      // 0..31
    int pl  = tid & 7;       // 0..7
    int d   = d0 + dl;
    const float* fb = feat + (long)(b * D_CH + d) * (OH * OW);

    __shared__ float tile[32][25];

    for (int p = pl; p < 25; p += 8) {
        int iy = p / 5, jx = p % 5;
        float xs = x1 + (jx + 0.5f) * bw;
        float ys = y1 + (iy + 0.5f) * bh;
        float x0f = floorf(xs), y0f = floorf(ys);
        float lx = xs - x0f,  ly = ys - y0f;
        int x0 = (int)x0f,    y0 = (int)y0f;
        int x0i = min(max(x0, 0), OW - 1);
        int x1i = min(max(x0 + 1, 0), OW - 1);
        int y0i = min(max(y0, 0), OH - 1);
        int y1i = min(max(y0 + 1, 0), OH - 1);
        float v00 = fb[y0i * OW + x0i];
        float v01 = fb[y0i * OW + x1i];
        float v10 = fb[y1i * OW + x0i];
        float v11 = fb[y1i * OW + x1i];
        float wy0 = 1.f - ly, wx0 = 1.f - lx;
        tile[dl][p] = v00 * wy0 * wx0 + v01 * wy0 * lx
                    + v10 * ly  * wx0 + v11 * ly  * lx;
    }
    __syncthreads();
    // coalesced write of 32 channels x 25 points = 800 contiguous floats
    float* dst = roi + (long)r * KDIM + d0 * 25;
    const float* src = &tile[0][0];
    for (int t = tid; t < 800; t += 256) dst[t] = src[t];
}

// =====================================================================
// 2) Generic fp32 tiled GEMM  C[z] = A[M,K] * B^T (B row-major [N,ldb])
//    tile 32x128, 256 thr, micro 2x8, reg-prefetch pipelining.
//    z selects: k-range (kZstride), B column offset (bZoff), C slot (cZstride)
// =====================================================================
#define GM 32
#define GN 128
#define GKC 32
__global__ __launch_bounds__(256) void gemm_kernel(
    const float* __restrict__ A, int lda,
    const float* __restrict__ B, int ldb, int bZoff,
    float* __restrict__ C, int cZstride,
    int M, int kLen, int kZstride)
{
    const int N = NFB;
    int nt = blockIdx.x, mt = blockIdx.y, z = blockIdx.z;
    B += (long)z * bZoff;
    C += (long)z * cZstride;
    int kBase = z * kZstride;
    int m0 = mt * GM, n0 = nt * GN;

    __shared__ float As[GKC][GM + 2];   // stride 34 -> float2 reads stay aligned
    __shared__ float Bs[GKC][GN + 4];

    int tid = threadIdx.x;
    int ty = tid >> 4, tx = tid & 15;          // compute map: rows 2, cols 8
    int lr = tid >> 3, lk = (tid & 7) << 2;    // load map

    float acc[2][8];
#pragma unroll
    for (int r = 0; r < 2; ++r)
#pragma unroll
        for (int j = 0; j < 8; ++j) acc[r][j] = 0.f;

    int nChunks = kLen / GKC;
    float4 aR; float4 bR[4];

    {   // prefetch chunk 0
        int k  = kBase + lk;
        int am = m0 + lr;
        aR = (am < M) ? *(const float4*)(A + (long)am * lda + k)
                      : make_float4(0.f, 0.f, 0.f, 0.f);
#pragma unroll
        for (int p = 0; p < 4; ++p) {
            int bn = n0 + lr + p * 32;
            bR[p] = *(const float4*)(B + (long)bn * ldb + k);
        }
    }

    for (int c = 0; c < nChunks; ++c) {
        __syncthreads();
        As[lk + 0][lr] = aR.x; As[lk + 1][lr] = aR.y;
        As[lk + 2][lr] = aR.z; As[lk + 3][lr] = aR.w;
#pragma unroll
        for (int p = 0; p < 4; ++p) {
            int bn = lr + p * 32;
            Bs[lk + 0][bn] = bR[p].x; Bs[lk + 1][bn] = bR[p].y;
            Bs[lk + 2][bn] = bR[p].z; Bs[lk + 3][bn] = bR[p].w;
        }
        __syncthreads();

        if (c + 1 < nChunks) {   // prefetch next chunk into regs (hides LDG)
            int k  = kBase + (c + 1) * GKC + lk;
            int am = m0 + lr;
            aR = (am < M) ? *(const float4*)(A + (long)am * lda + k)
                          : make_float4(0.f, 0.f, 0.f, 0.f);
#pragma unroll
            for (int p = 0; p < 4; ++p) {
                int bn = n0 + lr + p * 32;
                bR[p] = *(const float4*)(B + (long)bn * ldb + k);
            }
        }

#pragma unroll
        for (int k = 0; k < GKC; ++k) {
            float2 a  = *(const float2*)&As[k][ty * 2];
            float4 b0 = *(const float4*)&Bs[k][tx * 8];
            float4 b1 = *(const float4*)&Bs[k][tx * 8 + 4];
            acc[0][0] = fmaf(a.x, b0.x, acc[0][0]);
            acc[0][1] = fmaf(a.x, b0.y, acc[0][1]);
            acc[0][2] = fmaf(a.x, b0.z, acc[0][2]);
            acc[0][3] = fmaf(a.x, b0.w, acc[0][3]);
            acc[0][4] = fmaf(a.x, b1.x, acc[0][4]);
            acc[0][5] = fmaf(a.x, b1.y, acc[0][5]);
            acc[0][6] = fmaf(a.x, b1.z, acc[0][6]);
            acc[0][7] = fmaf(a.x, b1.w, acc[0][7]);
            acc[1][0] = fmaf(a.y, b0.x, acc[1][0]);
            acc[1][1] = fmaf(a.y, b0.y, acc[1][1]);
            acc[1][2] = fmaf(a.y, b0.z, acc[1][2]);
            acc[1][3] = fmaf(a.y, b0.w, acc[1][3]);
            acc[1][4] = fmaf(a.y, b1.x, acc[1][4]);
            acc[1][5] = fmaf(a.y, b1.y, acc[1][5]);
            acc[1][6] = fmaf(a.y, b1.z, acc[1][6]);
            acc[1][7] = fmaf(a.y, b1.w, acc[1][7]);
        }
    }

#pragma unroll
    for (int r = 0; r < 2; ++r) {
        int m = m0 + ty * 2 + r;
        if (m < M) {
            float4 o0 = make_float4(acc[r][0], acc[r][1], acc[r][2], acc[r][3]);
            float4 o1 = make_float4(acc[r][4], acc[r][5], acc[r][6], acc[r][7]);
            *(float4*)(C + (long)m * N + n0 + tx * 8)     = o0;
            *(float4*)(C + (long)m * N + n0 + tx * 8 + 4) = o1;
        }
    }
}

// =====================================================================
// 3) split-K reduce + bias + LayerNorm + ReLU + action head (fused)
//    grid 208, 256 thr, 4 cols/thread
// =====================================================================
__global__ __launch_bounds__(256) void ln_act_kernel(
    const float* __restrict__ partial,
    const float* __restrict__ b_emb,
    const float* __restrict__ ln_g, const float* __restrict__ ln_b,
    const float* __restrict__ W_act, const float* __restrict__ b_act,
    float* __restrict__ feats, float* __restrict__ out_act)
{
    int m = blockIdx.x, tid = threadIdx.x;
    int c = tid * 4;
    int lane = tid & 31, wid = tid >> 5;
    __shared__ float sred[48];

    float4 v = *(const float4*)(b_emb + c);
#pragma unroll
    for (int s = 0; s < EMB_SPLITS; ++s) {
        float4 p = *(const float4*)(partial + ((long)s * R_TOT + m) * NFB + c);
        v.x += p.x; v.y += p.y; v.z += p.z; v.w += p.w;
    }

    float S  = v.x + v.y + v.z + v.w;
    float SS = v.x*v.x + v.y*v.y + v.z*v.z + v.w*v.w;
#pragma unroll
    for (int o = 16; o; o >>= 1) {
        S  += __shfl_down_sync(0xffffffffu, S,  o);
        SS += __shfl_down_sync(0xffffffffu, SS, o);
    }
    if (lane == 0) { sred[wid * 2] = S; sred[wid * 2 + 1] = SS; }
    __syncthreads();
    float tS = 0.f, tSS = 0.f;
#pragma unroll
    for (int w = 0; w < 8; ++w) { tS += sred[w * 2]; tSS += sred[w * 2 + 1]; }
    float mean = tS * (1.0f / NFB);
    float var  = tSS * (1.0f / NFB) - mean * mean;
    float rstd = rsqrtf(var + 1e-5f);

    float4 g = *(const float4*)(ln_g + c);
    float4 bb = *(const float4*)(ln_b + c);
    float f0 = fmaxf((v.x - mean) * rstd * g.x + bb.x, 0.f);
    float f1 = fmaxf((v.y - mean) * rstd * g.y + bb.y, 0.f);
    float f2 = fmaxf((v.z - mean) * rstd * g.z + bb.z, 0.f);
    float f3 = fmaxf((v.w - mean) * rstd * g.w + bb.w, 0.f);
    *(float4*)(feats + (long)m * NFB + c) = make_float4(f0, f1, f2, f3);

    float a[NA];
#pragma unroll
    for (int o = 0; o < NA; ++o) {
        float4 w = *(const float4*)(W_act + (long)o * NFB + c);
        a[o] = f0 * w.x + f1 * w.y + f2 * w.z + f3 * w.w;
    }
    __syncthreads();   // before smem reuse
#pragma unroll
    for (int o = 0; o < NA; ++o) {
#pragma unroll
        for (int s = 16; s; s >>= 1) a[o] += __shfl_down_sync(0xffffffffu, a[o], s);
        if (lane == 0) sred[wid * NA + o] = a[o];
    }
    __syncthreads();
    if (tid < NA) {
        float s = 0.f;
#pragma unroll
        for (int w = 0; w < 8; ++w) s += sred[w * NA + tid];
        out_act[m * NA + tid] = s + b_act[tid];
    }
}

// =====================================================================
// 4) pairwise interaction: inter[p,o] = sum_f relu(U[i]+V[j]+b_i1) * W_i2[o]
//    grid 2496, 256 thr
// =====================================================================
__global__ __launch_bounds__(256) void pair_kernel(
    const float* __restrict__ UV,
    const float* __restrict__ b_i1,
    const float* __restrict__ W_i2, const float* __restrict__ b_i2,
    float* __restrict__ out)
{
    int p = blockIdx.x;
    int b = p / NPAIR_B, q = p % NPAIR_B;
    int i = q / (MAXN - 1), jj = q % (MAXN - 1);
    int j = jj + (jj >= i ? 1 : 0);
    const float* U = UV + (long)(b * MAXN + i) * NFB;
    const float* V = UV + (long)R_TOT * NFB + (long)(b * MAXN + j) * NFB;

    int tid = threadIdx.x, lane = tid & 31, wid = tid >> 5;
    int c = tid * 4;
    __shared__ float sred[16];

    float4 u  = *(const float4*)(U + c);
    float4 v  = *(const float4*)(V + c);
    float4 bi = *(const float4*)(b_i1 + c);
    float4 w0 = *(const float4*)(W_i2 + c);
    float4 w1 = *(const float4*)(W_i2 + NFB + c);

    float t0 = fmaxf(u.x + v.x + bi.x, 0.f);
    float t1 = fmaxf(u.y + v.y + bi.y, 0.f);
    float t2 = fmaxf(u.z + v.z + bi.z, 0.f);
    float t3 = fmaxf(u.w + v.w + bi.w, 0.f);
    float a0 = t0 * w0.x + t1 * w0.y + t2 * w0.z + t3 * w0.w;
    float a1 = t0 * w1.x + t1 * w1.y + t2 * w1.z + t3 * w1.w;

#pragma unroll
    for (int s = 16; s; s >>= 1) {
        a0 += __shfl_down_sync(0xffffffffu, a0, s);
        a1 += __shfl_down_sync(0xffffffffu, a1, s);
    }
    if (lane == 0) { sred[wid * 2] = a0; sred[wid * 2 + 1] = a1; }
    __syncthreads();
    if (tid < 2) {
        float s = 0.f;
#pragma unroll
        for (int w = 0; w < 8; ++w) s += sred[w * 2 + tid];
        out[p * 2 + tid] = s + b_i2[tid];
    }
}

// =====================================================================
// launch
// =====================================================================
extern "C" void kernel_launch(void* const* d_in, const int* in_sizes, int n_in,
                              void* d_out, int out_size)
{
    const float* features = (const float*)d_in[0];
    const float* boxes    = (const float*)d_in[1];
    // d_in[2] = bboxes_num_in (unused by reference math)
    const float* W_emb = (const float*)d_in[3];
    const float* b_emb = (const float*)d_in[4];
    const float* ln_g  = (const float*)d_in[5];
    const float* ln_b  = (const float*)d_in[6];
    const float* W_act = (const float*)d_in[7];
    const float* b_act = (const float*)d_in[8];
    const float* W_i1  = (const float*)d_in[9];
    const float* b_i1  = (const float*)d_in[10];
    const float* W_i2  = (const float*)d_in[11];
    const float* b_i2  = (const float*)d_in[12];
    float* out = (float*)d_out;

    void *roiP, *partP, *featP, *uvP;
    cudaGetSymbolAddress(&roiP,  g_roi);
    cudaGetSymbolAddress(&partP, g_part);
    cudaGetSymbolAddress(&featP, g_feats);
    cudaGetSymbolAddress(&uvP,   g_UV);
    float* roi   = (float*)roiP;
    float* part  = (float*)partP;
    float* feats = (float*)featP;
    float* uv    = (float*)uvP;

    // 1) ROI align
    roi_align_kernel<<<dim3(D_CH / 32, R_TOT), 256>>>(features, boxes, roi);

    // 2) embedding GEMM, split-K=25 (1056 K each = 33 chunks of 32)
    gemm_kernel<<<dim3(NFB / GN, (R_TOT + GM - 1) / GM, EMB_SPLITS), 256>>>(
        roi, KDIM, W_emb, KDIM, 0, part, R_TOT * NFB,
        R_TOT, KDIM / EMB_SPLITS, KDIM / EMB_SPLITS);

    // 3) reduce + LN + ReLU + action scores (first 1248 floats of d_out)
    ln_act_kernel<<<R_TOT, 256>>>(part, b_emb, ln_g, ln_b, W_act, b_act,
                                  feats, out);

    // 4) U = feats@A1^T (z=0), V = feats@A2^T (z=1); A1/A2 = W_i1 col halves
    gemm_kernel<<<dim3(NFB / GN, (R_TOT + GM - 1) / GM, 2), 256>>>(
        feats, NFB, W_i1, 2 * NFB, NFB, uv, R_TOT * NFB,
        R_TOT, NFB, 0);

    // 5) pairwise combine + interaction head (floats 1248..6239 of d_out)
    pair_kernel<<<NPAIR, 256>>>(uv, b_i1, W_i2, b_i2, out + R_TOT * NA);
}

// round 3
// speedup vs baseline: 2.8504x; 2.8504x over previous
#include <cuda_runtime.h>
#include <cuda_bf16.h>
#include <cstdint>

// ---------------- problem constants ----------------
#define BT    16
#define D_CH  1056
#define OH    57
#define OW    87
#define MAXN  13
#define KK    5
#define NFB   1024
#define NA    6
#define R_TOT 208
#define KDIM  26400
#define KPAD_E 26624              // 832 * 32
#define KSPLIT 8
#define KT_E   (KPAD_E/32/KSPLIT) // 104 k-chunks (of 32) per split
#define KPAD_U 1024
#define KT_U   (KPAD_U/32)        // 32
#define NPAIR_B 156
#define NPAIR   2496
#define MROWS 256

// ---------------- scratch (device globals; zero-initialized) ----------------
__device__ __align__(16) __nv_bfloat16 g_Ae_h[MROWS * KPAD_E];
__device__ __align__(16) __nv_bfloat16 g_Ae_l[MROWS * KPAD_E];
__device__ __align__(16) __nv_bfloat16 g_Be_h[NFB * KPAD_E];
__device__ __align__(16) __nv_bfloat16 g_Be_l[NFB * KPAD_E];
__device__ __align__(16) __nv_bfloat16 g_Bu_h[2 * NFB * KPAD_U];
__device__ __align__(16) __nv_bfloat16 g_Bu_l[2 * NFB * KPAD_U];
__device__ __align__(16) __nv_bfloat16 g_f_h [MROWS * NFB];
__device__ __align__(16) __nv_bfloat16 g_f_l [MROWS * NFB];
__device__ float g_part[KSPLIT * R_TOT * NFB];
__device__ float g_UV  [R_TOT * 2 * NFB];

// ---------------- helpers ----------------
__device__ __forceinline__ uint32_t smem_u32(const void* p) {
    uint32_t a;
    asm("{ .reg .u64 t; cvta.to.shared.u64 t, %1; cvt.u32.u64 %0, t; }"
        : "=r"(a) : "l"(p));
    return a;
}
__device__ __forceinline__ void cp16(uint32_t dst, const void* src) {
    asm volatile("cp.async.cg.shared.global [%0], [%1], 16;" :: "r"(dst), "l"(src));
}
#define CP_COMMIT() asm volatile("cp.async.commit_group;" ::: "memory")

#define LDM4(R, addr) \
    asm volatile("ldmatrix.sync.aligned.m8n8.x4.shared.b16 {%0,%1,%2,%3}, [%4];" \
        : "=r"((R)[0]), "=r"((R)[1]), "=r"((R)[2]), "=r"((R)[3]) : "r"(addr))

#define MMA(D, A, B0, B1) \
    asm volatile("mma.sync.aligned.m16n8k16.row.col.f32.bf16.bf16.f32 " \
        "{%0,%1,%2,%3}, {%4,%5,%6,%7}, {%8,%9}, {%0,%1,%2,%3};" \
        : "+f"((D)[0]), "+f"((D)[1]), "+f"((D)[2]), "+f"((D)[3]) \
        : "r"((A)[0]), "r"((A)[1]), "r"((A)[2]), "r"((A)[3]), "r"(B0), "r"(B1))

__device__ __forceinline__ void split_bf16(float x, __nv_bfloat16& h, __nv_bfloat16& l) {
    h = __float2bfloat16(x);
    l = __float2bfloat16(x - __bfloat162float(h));
}

// =====================================================================
// converters
// =====================================================================
__global__ __launch_bounds__(256) void conv_wemb(
    const float* __restrict__ W, __nv_bfloat16* __restrict__ oh,
    __nv_bfloat16* __restrict__ ol)
{
    int f = blockIdx.y;
    int k = blockIdx.x * 256 + threadIdx.x;
    __nv_bfloat16 h = __float2bfloat16(0.f), l = h;
    if (k < KDIM) split_bf16(W[(size_t)f * KDIM + k], h, l);
    size_t o = (size_t)f * KPAD_E + k;
    oh[o] = h; ol[o] = l;
}
__global__ __launch_bounds__(256) void conv_wi1(
    const float* __restrict__ W, __nv_bfloat16* __restrict__ oh,
    __nv_bfloat16* __restrict__ ol)
{
    int f = blockIdx.y;                                // 0..2047
    int k = blockIdx.x * 256 + threadIdx.x;            // 0..1023
    float v = (f < NFB) ? W[(size_t)f * (2 * NFB) + k]
                        : W[(size_t)(f - NFB) * (2 * NFB) + NFB + k];
    __nv_bfloat16 h, l; split_bf16(v, h, l);
    size_t o = (size_t)f * KPAD_U + k;
    oh[o] = h; ol[o] = l;
}
__global__ __launch_bounds__(256) void zero_padA(
    __nv_bfloat16* __restrict__ ah, __nv_bfloat16* __restrict__ al)
{
    int r = blockIdx.x;
    int t = threadIdx.x;
    if (t < KPAD_E - KDIM) {
        size_t o = (size_t)r * KPAD_E + KDIM + t;
        ah[o] = __float2bfloat16(0.f);
        al[o] = __float2bfloat16(0.f);
    }
}

// =====================================================================
// ROI align -> bf16 hi/lo A operand
// =====================================================================
__global__ __launch_bounds__(256) void roi_align_kernel(
    const float* __restrict__ feat, const float* __restrict__ boxes,
    __nv_bfloat16* __restrict__ ah, __nv_bfloat16* __restrict__ al)
{
    int r  = blockIdx.y;
    int d0 = blockIdx.x * 32;
    int b  = r / MAXN;
    const float* bx = boxes + r * 4;
    float x1 = bx[0], y1 = bx[1], x2 = bx[2], y2 = bx[3];
    float bw = (x2 - x1) * (1.0f / KK);
    float bh = (y2 - y1) * (1.0f / KK);

    int tid = threadIdx.x;
    int dl = tid >> 3, pl = tid & 7;
    const float* fb = feat + (size_t)(b * D_CH + d0 + dl) * (OH * OW);

    __shared__ float tile[32][25];
    for (int p = pl; p < 25; p += 8) {
        int iy = p / 5, jx = p % 5;
        float xs = x1 + (jx + 0.5f) * bw;
        float ys = y1 + (iy + 0.5f) * bh;
        float x0f = floorf(xs), y0f = floorf(ys);
        float lx = xs - x0f, ly = ys - y0f;
        int x0 = (int)x0f, y0 = (int)y0f;
        int x0i = min(max(x0, 0), OW - 1);
        int x1i = min(max(x0 + 1, 0), OW - 1);
        int y0i = min(max(y0, 0), OH - 1);
        int y1i = min(max(y0 + 1, 0), OH - 1);
        float v00 = fb[y0i * OW + x0i], v01 = fb[y0i * OW + x1i];
        float v10 = fb[y1i * OW + x0i], v11 = fb[y1i * OW + x1i];
        float wy0 = 1.f - ly, wx0 = 1.f - lx;
        tile[dl][p] = v00 * wy0 * wx0 + v01 * wy0 * lx
                    + v10 * ly  * wx0 + v11 * ly  * lx;
    }
    __syncthreads();
    size_t base = (size_t)r * KPAD_E + d0 * 25;
    const float* src = &tile[0][0];
    for (int t = tid; t < 800; t += 256) {
        __nv_bfloat16 h, l; split_bf16(src[t], h, l);
        ah[base + t] = h; al[base + t] = l;
    }
}

// =====================================================================
// HMMA bf16x3-split GEMM: C[z] = A * B^T
//   block tile 64(M) x 128(N) x 32(K), 256 thr (8 warps: 2M x 4N),
//   double-buffered cp.async, smem row stride 80B (conflict-free ldmatrix)
// =====================================================================
#define ROWB 80              // smem row stride in bytes (32 bf16 + 8 pad)
#define AH_OFF 0
#define AL_OFF (64 * ROWB)                 // 5120
#define BH_OFF (2 * 64 * ROWB)             // 10240
#define BL_OFF (BH_OFF + 128 * ROWB)       // 20480
#define STAGE_SZ (BL_OFF + 128 * ROWB)     // 30720
#define SMEM_DYN (2 * STAGE_SZ)            // 61440

__global__ __launch_bounds__(256, 2) void hmma_gemm(
    const __nv_bfloat16* __restrict__ Ah, const __nv_bfloat16* __restrict__ Al,
    const __nv_bfloat16* __restrict__ Bh, const __nv_bfloat16* __restrict__ Bl,
    int kPad, int kTiles, float* __restrict__ C, long cZstride,
    int Nld, int Mreal)
{
    extern __shared__ char smraw[];
    const uint32_t sm = smem_u32(smraw);
    const int tid = threadIdx.x;
    const int lane = tid & 31, wid = tid >> 5;
    const int wm = wid & 1, wn = wid >> 1;          // 2 M-warps x 4 N-warps
    const int n0 = blockIdx.x * 128, m0 = blockIdx.y * 64, z = blockIdx.z;
    const long k00 = (long)z * kTiles * 32;
    C += (long)z * cZstride;

    // ---- load maps (per thread: 1 A-row-chunk x2 mats, 2 B-row-chunks x2 mats)
    const int lrow = tid >> 2, lc = tid & 3;        // lrow 0..63, lc 0..3
    const __nv_bfloat16* aHp = Ah + (size_t)(m0 + lrow) * kPad + lc * 8;
    const __nv_bfloat16* aLp = Al + (size_t)(m0 + lrow) * kPad + lc * 8;
    const __nv_bfloat16* bHp0 = Bh + (size_t)(n0 + lrow) * kPad + lc * 8;
    const __nv_bfloat16* bLp0 = Bl + (size_t)(n0 + lrow) * kPad + lc * 8;
    const __nv_bfloat16* bHp1 = Bh + (size_t)(n0 + 64 + lrow) * kPad + lc * 8;
    const __nv_bfloat16* bLp1 = Bl + (size_t)(n0 + 64 + lrow) * kPad + lc * 8;
    const uint32_t aDst = lrow * ROWB + lc * 16;
    const uint32_t bDst0 = lrow * ROWB + lc * 16;
    const uint32_t bDst1 = (64 + lrow) * ROWB + lc * 16;

    // ---- ldmatrix address bases (per lane)
    const uint32_t aLdm = sm + (wm * 32 + (lane & 15)) * ROWB + (lane >> 4) * 16;
    const uint32_t bLdm = sm + (wn * 32 + (lane & 15)) * ROWB + (lane >> 4) * 16;

    float d[2][4][4];
#pragma unroll
    for (int mi = 0; mi < 2; ++mi)
#pragma unroll
        for (int ni = 0; ni < 4; ++ni)
#pragma unroll
            for (int q = 0; q < 4; ++q) d[mi][ni][q] = 0.f;

    auto load_stage = [&](int s, int kt) {
        long ke = k00 + (long)kt * 32;
        uint32_t st = sm + s * STAGE_SZ;
        cp16(st + AH_OFF + aDst, aHp + ke);
        cp16(st + AL_OFF + aDst, aLp + ke);
        cp16(st + BH_OFF + bDst0, bHp0 + ke);
        cp16(st + BH_OFF + bDst1, bHp1 + ke);
        cp16(st + BL_OFF + bDst0, bLp0 + ke);
        cp16(st + BL_OFF + bDst1, bLp1 + ke);
        CP_COMMIT();
    };

    load_stage(0, 0);

    for (int kt = 0; kt < kTiles; ++kt) {
        int s = kt & 1;
        if (kt + 1 < kTiles) {
            load_stage(s ^ 1, kt + 1);
            asm volatile("cp.async.wait_group 1;" ::: "memory");
        } else {
            asm volatile("cp.async.wait_group 0;" ::: "memory");
        }
        __syncthreads();

        uint32_t stA = aLdm + s * STAGE_SZ;
        uint32_t stB = bLdm + s * STAGE_SZ;
#pragma unroll
        for (int ks = 0; ks < 2; ++ks) {
            uint32_t ah[2][4], al_[2][4], bh[2][4], bl_[2][4];
#pragma unroll
            for (int mi = 0; mi < 2; ++mi) {
                uint32_t ad = stA + mi * (16 * ROWB) + ks * 32;
                LDM4(ah[mi],  ad + AH_OFF);
                LDM4(al_[mi], ad + AL_OFF);
            }
#pragma unroll
            for (int pr = 0; pr < 2; ++pr) {
                uint32_t bd = stB + pr * (16 * ROWB) + ks * 32;
                LDM4(bh[pr],  bd + BH_OFF);
                LDM4(bl_[pr], bd + BL_OFF);
            }
#pragma unroll
            for (int mi = 0; mi < 2; ++mi) {
#pragma unroll
                for (int ni = 0; ni < 4; ++ni) {
                    int pr = ni >> 1, hi = ni & 1;
                    MMA(d[mi][ni], ah[mi],  bh[pr][hi], bh[pr][hi + 2]);
                    MMA(d[mi][ni], ah[mi],  bl_[pr][hi], bl_[pr][hi + 2]);
                    MMA(d[mi][ni], al_[mi], bh[pr][hi], bh[pr][hi + 2]);
                }
            }
        }
        __syncthreads();
    }

    // ---- epilogue
#pragma unroll
    for (int mi = 0; mi < 2; ++mi) {
        int r0 = m0 + wm * 32 + mi * 16 + (lane >> 2);
        int r1 = r0 + 8;
#pragma unroll
        for (int ni = 0; ni < 4; ++ni) {
            int col = n0 + wn * 32 + ni * 8 + (lane & 3) * 2;
            if (r0 < Mreal)
                *(float2*)(C + (size_t)r0 * Nld + col) = make_float2(d[mi][ni][0], d[mi][ni][1]);
            if (r1 < Mreal)
                *(float2*)(C + (size_t)r1 * Nld + col) = make_float2(d[mi][ni][2], d[mi][ni][3]);
        }
    }
}

// =====================================================================
// split-K reduce + bias + LayerNorm + ReLU + action head; emits bf16 hi/lo
// =====================================================================
__global__ __launch_bounds__(256) void ln_act_kernel(
    const float* __restrict__ partial, const float* __restrict__ b_emb,
    const float* __restrict__ ln_g, const float* __restrict__ ln_b,
    const float* __restrict__ W_act, const float* __restrict__ b_act,
    __nv_bfloat16* __restrict__ fH, __nv_bfloat16* __restrict__ fL,
    float* __restrict__ out_act)
{
    int m = blockIdx.x, tid = threadIdx.x;
    int c = tid * 4;
    int lane = tid & 31, wid = tid >> 5;
    __shared__ float sred[48];

    float4 v = *(const float4*)(b_emb + c);
#pragma unroll
    for (int s = 0; s < KSPLIT; ++s) {
        float4 p = *(const float4*)(partial + ((size_t)s * R_TOT + m) * NFB + c);
        v.x += p.x; v.y += p.y; v.z += p.z; v.w += p.w;
    }
    float S = v.x + v.y + v.z + v.w;
    float SS = v.x * v.x + v.y * v.y + v.z * v.z + v.w * v.w;
#pragma unroll
    for (int o = 16; o; o >>= 1) {
        S  += __shfl_down_sync(0xffffffffu, S,  o);
        SS += __shfl_down_sync(0xffffffffu, SS, o);
    }
    if (lane == 0) { sred[wid * 2] = S; sred[wid * 2 + 1] = SS; }
    __syncthreads();
    float tS = 0.f, tSS = 0.f;
#pragma unroll
    for (int w = 0; w < 8; ++w) { tS += sred[w * 2]; tSS += sred[w * 2 + 1]; }
    float mean = tS * (1.0f / NFB);
    float var  = tSS * (1.0f / NFB) - mean * mean;
    float rstd = rsqrtf(var + 1e-5f);

    float4 g = *(const float4*)(ln_g + c);
    float4 bb = *(const float4*)(ln_b + c);
    float f0 = fmaxf((v.x - mean) * rstd * g.x + bb.x, 0.f);
    float f1 = fmaxf((v.y - mean) * rstd * g.y + bb.y, 0.f);
    float f2 = fmaxf((v.z - mean) * rstd * g.z + bb.z, 0.f);
    float f3 = fmaxf((v.w - mean) * rstd * g.w + bb.w, 0.f);

    size_t fo = (size_t)m * NFB + c;
    __nv_bfloat16 h, l;
    split_bf16(f0, h, l); fH[fo + 0] = h; fL[fo + 0] = l;
    split_bf16(f1, h, l); fH[fo + 1] = h; fL[fo + 1] = l;
    split_bf16(f2, h, l); fH[fo + 2] = h; fL[fo + 2] = l;
    split_bf16(f3, h, l); fH[fo + 3] = h; fL[fo + 3] = l;

    float a[NA];
#pragma unroll
    for (int o = 0; o < NA; ++o) {
        float4 w = *(const float4*)(W_act + (size_t)o * NFB + c);
        a[o] = f0 * w.x + f1 * w.y + f2 * w.z + f3 * w.w;
    }
    __syncthreads();
#pragma unroll
    for (int o = 0; o < NA; ++o) {
#pragma unroll
        for (int s = 16; s; s >>= 1) a[o] += __shfl_down_sync(0xffffffffu, a[o], s);
        if (lane == 0) sred[wid * NA + o] = a[o];
    }
    __syncthreads();
    if (tid < NA) {
        float s = 0.f;
#pragma unroll
        for (int w = 0; w < 8; ++w) s += sred[w * NA + tid];
        out_act[m * NA + tid] = s + b_act[tid];
    }
}

// =====================================================================
// pairwise interaction from U/V (UV layout [208][2048], V at col 1024)
// =====================================================================
__global__ __launch_bounds__(256) void pair_kernel(
    const float* __restrict__ UV, const float* __restrict__ b_i1,
    const float* __restrict__ W_i2, const float* __restrict__ b_i2,
    float* __restrict__ out)
{
    int p = blockIdx.x;
    int b = p / NPAIR_B, q = p % NPAIR_B;
    int i = q / (MAXN - 1), jj = q % (MAXN - 1);
    int j = jj + (jj >= i ? 1 : 0);
    const float* U = UV + (size_t)(b * MAXN + i) * (2 * NFB);
    const float* V = UV + (size_t)(b * MAXN + j) * (2 * NFB) + NFB;

    int tid = threadIdx.x, lane = tid & 31, wid = tid >> 5;
    int c = tid * 4;
    __shared__ float sred[16];

    float4 u  = *(const float4*)(U + c);
    float4 v  = *(const float4*)(V + c);
    float4 bi = *(const float4*)(b_i1 + c);
    float4 w0 = *(const float4*)(W_i2 + c);
    float4 w1 = *(const float4*)(W_i2 + NFB + c);

    float t0 = fmaxf(u.x + v.x + bi.x, 0.f);
    float t1 = fmaxf(u.y + v.y + bi.y, 0.f);
    float t2 = fmaxf(u.z + v.z + bi.z, 0.f);
    float t3 = fmaxf(u.w + v.w + bi.w, 0.f);
    float a0 = t0 * w0.x + t1 * w0.y + t2 * w0.z + t3 * w0.w;
    float a1 = t0 * w1.x + t1 * w1.y + t2 * w1.z + t3 * w1.w;
#pragma unroll
    for (int s = 16; s; s >>= 1) {
        a0 += __shfl_down_sync(0xffffffffu, a0, s);
        a1 += __shfl_down_sync(0xffffffffu, a1, s);
    }
    if (lane == 0) { sred[wid * 2] = a0; sred[wid * 2 + 1] = a1; }
    __syncthreads();
    if (tid < 2) {
        float s = 0.f;
#pragma unroll
        for (int w = 0; w < 8; ++w) s += sred[w * 2 + tid];
        out[p * 2 + tid] = s + b_i2[tid];
    }
}

// =====================================================================
// launch
// =====================================================================
extern "C" void kernel_launch(void* const* d_in, const int* in_sizes, int n_in,
                              void* d_out, int out_size)
{
    const float* features = (const float*)d_in[0];
    const float* boxes    = (const float*)d_in[1];
    const float* W_emb = (const float*)d_in[3];
    const float* b_emb = (const float*)d_in[4];
    const float* ln_g  = (const float*)d_in[5];
    const float* ln_b  = (const float*)d_in[6];
    const float* W_act = (const float*)d_in[7];
    const float* b_act = (const float*)d_in[8];
    const float* W_i1  = (const float*)d_in[9];
    const float* b_i1  = (const float*)d_in[10];
    const float* W_i2  = (const float*)d_in[11];
    const float* b_i2  = (const float*)d_in[12];
    float* out = (float*)d_out;

    void *aeh, *ael, *beh, *bel, *buh, *bul, *fh, *fl, *pp, *uvp;
    cudaGetSymbolAddress(&aeh, g_Ae_h); cudaGetSymbolAddress(&ael, g_Ae_l);
    cudaGetSymbolAddress(&beh, g_Be_h); cudaGetSymbolAddress(&bel, g_Be_l);
    cudaGetSymbolAddress(&buh, g_Bu_h); cudaGetSymbolAddress(&bul, g_Bu_l);
    cudaGetSymbolAddress(&fh, g_f_h);   cudaGetSymbolAddress(&fl, g_f_l);
    cudaGetSymbolAddress(&pp, g_part);  cudaGetSymbolAddress(&uvp, g_UV);

    static int smem_set = 0;
    if (!smem_set) {
        cudaFuncSetAttribute(hmma_gemm, cudaFuncAttributeMaxDynamicSharedMemorySize, SMEM_DYN);
        smem_set = 1;
    }

    // operand prep
    conv_wemb<<<dim3(KPAD_E / 256, NFB), 256>>>(W_emb, (__nv_bfloat16*)beh, (__nv_bfloat16*)bel);
    conv_wi1 <<<dim3(KPAD_U / 256, 2 * NFB), 256>>>(W_i1, (__nv_bfloat16*)buh, (__nv_bfloat16*)bul);
    roi_align_kernel<<<dim3(D_CH / 32, R_TOT), 256>>>(features, boxes,
                                                      (__nv_bfloat16*)aeh, (__nv_bfloat16*)ael);
    zero_padA<<<R_TOT, 256>>>((__nv_bfloat16*)aeh, (__nv_bfloat16*)ael);

    // embedding GEMM: [208 x 26624] x [1024 x 26624]^T, split-K=8
    hmma_gemm<<<dim3(NFB / 128, 4, KSPLIT), 256, SMEM_DYN>>>(
        (const __nv_bfloat16*)aeh, (const __nv_bfloat16*)ael,
        (const __nv_bfloat16*)beh, (const __nv_bfloat16*)bel,
        KPAD_E, KT_E, (float*)pp, (long)R_TOT * NFB, NFB, R_TOT);

    // reduce + LN + ReLU + action head
    ln_act_kernel<<<R_TOT, 256>>>((const float*)pp, b_emb, ln_g, ln_b, W_act, b_act,
                                  (__nv_bfloat16*)fh, (__nv_bfloat16*)fl, out);

    // UV GEMM: [208 x 1024] x [2048 x 1024]^T -> UV [208][2048]
    hmma_gemm<<<dim3(2 * NFB / 128, 4, 1), 256, SMEM_DYN>>>(
        (const __nv_bfloat16*)fh, (const __nv_bfloat16*)fl,
        (const __nv_bfloat16*)buh, (const __nv_bfloat16*)bul,
        KPAD_U, KT_U, (float*)uvp, 0L, 2 * NFB, R_TOT);

    // pairwise combine + interaction head
    pair_kernel<<<NPAIR, 256>>>((const float*)uvp, b_i1, W_i2, b_i2, out + R_TOT * NA);
}

// round 4
// speedup vs baseline: 4.3321x; 1.5198x over previous
#include <cuda_runtime.h>
#include <cuda_fp16.h>
#include <cstdint>

// ---------------- problem constants ----------------
#define BT    16
#define D_CH  1056
#define OH    57
#define OW    87
#define MAXN  13
#define KK    5
#define NFB   1024
#define NA    6
#define R_TOT 208
#define KDIM  26400
#define KPAD_E 26624              // 832 * 32
#define KSPLIT 8
#define KT_E   (KPAD_E/32/KSPLIT) // 104 k-chunks (of 32) per split
#define KPAD_U 1024
#define KT_U   (KPAD_U/32)        // 32
#define NPAIR_B 156
#define NPAIR   2496
#define MROWS 256

// ---------------- scratch (device globals; zero-initialized) ----------------
__device__ __align__(16) __half g_Ae_h[MROWS * KPAD_E];
__device__ __align__(16) __half g_Ae_l[MROWS * KPAD_E];
__device__ __align__(16) __half g_Be  [NFB * KPAD_E];
__device__ __align__(16) __half g_Bu  [2 * NFB * KPAD_U];
__device__ __align__(16) __half g_f_h [MROWS * NFB];
__device__ __align__(16) __half g_f_l [MROWS * NFB];
__device__ float g_part[KSPLIT * R_TOT * NFB];
__device__ float g_UV  [R_TOT * 2 * NFB];

// ---------------- helpers ----------------
__device__ __forceinline__ uint32_t smem_u32(const void* p) {
    uint32_t a;
    asm("{ .reg .u64 t; cvta.to.shared.u64 t, %1; cvt.u32.u64 %0, t; }"
        : "=r"(a) : "l"(p));
    return a;
}
__device__ __forceinline__ void cp16(uint32_t dst, const void* src) {
    asm volatile("cp.async.cg.shared.global [%0], [%1], 16;" :: "r"(dst), "l"(src));
}
#define CP_COMMIT() asm volatile("cp.async.commit_group;" ::: "memory")

#define LDM4(R, addr) \
    asm volatile("ldmatrix.sync.aligned.m8n8.x4.shared.b16 {%0,%1,%2,%3}, [%4];" \
        : "=r"((R)[0]), "=r"((R)[1]), "=r"((R)[2]), "=r"((R)[3]) : "r"(addr))

#define MMA(D, A, B0, B1) \
    asm volatile("mma.sync.aligned.m16n8k16.row.col.f32.f16.f16.f32 " \
        "{%0,%1,%2,%3}, {%4,%5,%6,%7}, {%8,%9}, {%0,%1,%2,%3};" \
        : "+f"((D)[0]), "+f"((D)[1]), "+f"((D)[2]), "+f"((D)[3]) \
        : "r"((A)[0]), "r"((A)[1]), "r"((A)[2]), "r"((A)[3]), "r"(B0), "r"(B1))

__device__ __forceinline__ void split_h(float x, __half& h, __half& l) {
    h = __float2half_rn(x);
    l = __float2half_rn(x - __half2float(h));
}

// =====================================================================
// converters (vectorized: 8 elems/thread, 16B stores)
// =====================================================================
__global__ __launch_bounds__(256) void conv_wemb(
    const float* __restrict__ W, __half* __restrict__ o)
{
    int f = blockIdx.y;
    int k0 = (blockIdx.x * 256 + threadIdx.x) * 8;   // grid.x = 13 -> k0 < 26624
    __half h[8];
    const float* src = W + (size_t)f * KDIM + k0;
    if (k0 + 8 <= KDIM) {
        float4 v0 = *(const float4*)src;
        float4 v1 = *(const float4*)(src + 4);
        h[0] = __float2half_rn(v0.x); h[1] = __float2half_rn(v0.y);
        h[2] = __float2half_rn(v0.z); h[3] = __float2half_rn(v0.w);
        h[4] = __float2half_rn(v1.x); h[5] = __float2half_rn(v1.y);
        h[6] = __float2half_rn(v1.z); h[7] = __float2half_rn(v1.w);
    } else {
#pragma unroll
        for (int i = 0; i < 8; ++i)
            h[i] = (k0 + i < KDIM) ? __float2half_rn(src[i]) : __ushort_as_half(0);
    }
    *(uint4*)(o + (size_t)f * KPAD_E + k0) = *(const uint4*)h;
}

__global__ __launch_bounds__(128) void conv_wi1(
    const float* __restrict__ W, __half* __restrict__ o)
{
    int f = blockIdx.x;                              // 0..2047
    int k0 = threadIdx.x * 8;                        // 0..1016
    const float* src = (f < NFB) ? W + (size_t)f * (2 * NFB) + k0
                                 : W + (size_t)(f - NFB) * (2 * NFB) + NFB + k0;
    float4 v0 = *(const float4*)src;
    float4 v1 = *(const float4*)(src + 4);
    __half h[8];
    h[0] = __float2half_rn(v0.x); h[1] = __float2half_rn(v0.y);
    h[2] = __float2half_rn(v0.z); h[3] = __float2half_rn(v0.w);
    h[4] = __float2half_rn(v1.x); h[5] = __float2half_rn(v1.y);
    h[6] = __float2half_rn(v1.z); h[7] = __float2half_rn(v1.w);
    *(uint4*)(o + (size_t)f * KPAD_U + k0) = *(const uint4*)h;
}

// =====================================================================
// ROI align -> fp16 hi/lo A operand (+ pad-zero fold on blockIdx.x==0)
// =====================================================================
__global__ __launch_bounds__(256) void roi_align_kernel(
    const float* __restrict__ feat, const float* __restrict__ boxes,
    __half* __restrict__ ah, __half* __restrict__ al)
{
    int r  = blockIdx.y;
    int d0 = blockIdx.x * 32;
    int b  = r / MAXN;
    const float* bx = boxes + r * 4;
    float x1 = bx[0], y1 = bx[1], x2 = bx[2], y2 = bx[3];
    float bw = (x2 - x1) * (1.0f / KK);
    float bh = (y2 - y1) * (1.0f / KK);

    int tid = threadIdx.x;
    int dl = tid >> 3, pl = tid & 7;
    const float* fb = feat + (size_t)(b * D_CH + d0 + dl) * (OH * OW);

    __shared__ float tile[32][25];
    for (int p = pl; p < 25; p += 8) {
        int iy = p / 5, jx = p % 5;
        float xs = x1 + (jx + 0.5f) * bw;
        float ys = y1 + (iy + 0.5f) * bh;
        float x0f = floorf(xs), y0f = floorf(ys);
        float lx = xs - x0f, ly = ys - y0f;
        int x0 = (int)x0f, y0 = (int)y0f;
        int x0i = min(max(x0, 0), OW - 1);
        int x1i = min(max(x0 + 1, 0), OW - 1);
        int y0i = min(max(y0, 0), OH - 1);
        int y1i = min(max(y0 + 1, 0), OH - 1);
        float v00 = fb[y0i * OW + x0i], v01 = fb[y0i * OW + x1i];
        float v10 = fb[y1i * OW + x0i], v11 = fb[y1i * OW + x1i];
        float wy0 = 1.f - ly, wx0 = 1.f - lx;
        tile[dl][p] = v00 * wy0 * wx0 + v01 * wy0 * lx
                    + v10 * ly  * wx0 + v11 * ly  * lx;
    }
    __syncthreads();
    size_t base = (size_t)r * KPAD_E + d0 * 25;
    const float* src = &tile[0][0];
    for (int t = tid; t < 800; t += 256) {
        __half h, l; split_h(src[t], h, l);
        ah[base + t] = h; al[base + t] = l;
    }
    // fold pad-zero: cols [KDIM, KPAD_E) of row r (224 halves = 28 uint4)
    if (blockIdx.x == 0 && tid < 28) {
        uint4 z = make_uint4(0, 0, 0, 0);
        *(uint4*)(ah + (size_t)r * KPAD_E + KDIM + tid * 8) = z;
        *(uint4*)(al + (size_t)r * KPAD_E + KDIM + tid * 8) = z;
    }
}

// =====================================================================
// HMMA fp16 split-2 GEMM: C[z] = (Ah + Al) * B^T   (B pre-rounded fp16)
//   block tile 64(M) x 128(N) x 32(K), 8 warps (2M x 4N),
//   double-buffered cp.async, row stride 80B, dead-M-row skip
// =====================================================================
#define ROWB 80
#define AH_OFF 0
#define AL_OFF (64 * ROWB)              // 5120
#define B_OFF  (2 * 64 * ROWB)          // 10240
#define STAGE_SZ (B_OFF + 128 * ROWB)   // 20480
#define SMEM_DYN (2 * STAGE_SZ)         // 40960

__global__ __launch_bounds__(256, 3) void hmma_gemm(
    const __half* __restrict__ Ah, const __half* __restrict__ Al,
    const __half* __restrict__ B,
    int kPad, int kTiles, float* __restrict__ C, long cZstride,
    int Nld, int Mreal)
{
    extern __shared__ char smraw[];
    const uint32_t sm = smem_u32(smraw);
    const int tid = threadIdx.x;
    const int lane = tid & 31, wid = tid >> 5;
    const int wm = wid & 1, wn = wid >> 1;          // 2 M-warps x 4 N-warps
    const int n0 = blockIdx.x * 128, m0 = blockIdx.y * 64, z = blockIdx.z;
    const long k00 = (long)z * kTiles * 32;
    C += (long)z * cZstride;

    // per-warp activity (M blocks of 16; Mreal is a multiple of 16)
    const bool act0 = (m0 + wm * 32)      < Mreal;
    const bool act1 = (m0 + wm * 32 + 16) < Mreal;

    // ---- load maps
    const int lrow = tid >> 2, lc = tid & 3;        // lrow 0..63, lc 0..3
    const __half* aHp = Ah + (size_t)(m0 + lrow) * kPad + lc * 8;
    const __half* aLp = Al + (size_t)(m0 + lrow) * kPad + lc * 8;
    const __half* bP0 = B + (size_t)(n0 + lrow) * kPad + lc * 8;
    const __half* bP1 = B + (size_t)(n0 + 64 + lrow) * kPad + lc * 8;
    const uint32_t aDst = lrow * ROWB + lc * 16;
    const uint32_t bDst0 = lrow * ROWB + lc * 16;
    const uint32_t bDst1 = (64 + lrow) * ROWB + lc * 16;

    // ---- ldmatrix per-lane bases
    const uint32_t aLdm = sm + (wm * 32 + (lane & 15)) * ROWB + (lane >> 4) * 16;
    const uint32_t bLdm = sm + (wn * 32 + (lane & 15)) * ROWB + (lane >> 4) * 16;

    float d[2][4][4];
#pragma unroll
    for (int mi = 0; mi < 2; ++mi)
#pragma unroll
        for (int ni = 0; ni < 4; ++ni)
#pragma unroll
            for (int q = 0; q < 4; ++q) d[mi][ni][q] = 0.f;

    auto load_stage = [&](int s, int kt) {
        long ke = k00 + (long)kt * 32;
        uint32_t st = sm + s * STAGE_SZ;
        cp16(st + AH_OFF + aDst, aHp + ke);
        cp16(st + AL_OFF + aDst, aLp + ke);
        cp16(st + B_OFF + bDst0, bP0 + ke);
        cp16(st + B_OFF + bDst1, bP1 + ke);
        CP_COMMIT();
    };

    load_stage(0, 0);

    for (int kt = 0; kt < kTiles; ++kt) {
        int s = kt & 1;
        if (kt + 1 < kTiles) {
            load_stage(s ^ 1, kt + 1);
            asm volatile("cp.async.wait_group 1;" ::: "memory");
        } else {
            asm volatile("cp.async.wait_group 0;" ::: "memory");
        }
        __syncthreads();

        uint32_t stA = aLdm + s * STAGE_SZ;
        uint32_t stB = bLdm + s * STAGE_SZ;
#pragma unroll
        for (int ks = 0; ks < 2; ++ks) {
            uint32_t ah[2][4], al_[2][4], b[2][4];
#pragma unroll
            for (int pr = 0; pr < 2; ++pr)
                LDM4(b[pr], stB + B_OFF + pr * (16 * ROWB) + ks * 32);
            if (act0) {
                LDM4(ah[0],  stA + AH_OFF + ks * 32);
                LDM4(al_[0], stA + AL_OFF + ks * 32);
            }
            if (act1) {
                LDM4(ah[1],  stA + AH_OFF + 16 * ROWB + ks * 32);
                LDM4(al_[1], stA + AL_OFF + 16 * ROWB + ks * 32);
            }
#pragma unroll
            for (int mi = 0; mi < 2; ++mi) {
                if (mi == 0 ? !act0 : !act1) continue;
#pragma unroll
                for (int ni = 0; ni < 4; ++ni) {
                    int pr = ni >> 1, hi = ni & 1;
                    MMA(d[mi][ni], ah[mi],  b[pr][hi], b[pr][hi + 2]);
                    MMA(d[mi][ni], al_[mi], b[pr][hi], b[pr][hi + 2]);
                }
            }
        }
        __syncthreads();
    }

    // ---- epilogue
#pragma unroll
    for (int mi = 0; mi < 2; ++mi) {
        int r0 = m0 + wm * 32 + mi * 16 + (lane >> 2);
        int r1 = r0 + 8;
#pragma unroll
        for (int ni = 0; ni < 4; ++ni) {
            int col = n0 + wn * 32 + ni * 8 + (lane & 3) * 2;
            if (r0 < Mreal)
                *(float2*)(C + (size_t)r0 * Nld + col) = make_float2(d[mi][ni][0], d[mi][ni][1]);
            if (r1 < Mreal)
                *(float2*)(C + (size_t)r1 * Nld + col) = make_float2(d[mi][ni][2], d[mi][ni][3]);
        }
    }
}

// =====================================================================
// split-K reduce + bias + LayerNorm + ReLU + action head; emits fp16 hi/lo
// =====================================================================
__global__ __launch_bounds__(256) void ln_act_kernel(
    const float* __restrict__ partial, const float* __restrict__ b_emb,
    const float* __restrict__ ln_g, const float* __restrict__ ln_b,
    const float* __restrict__ W_act, const float* __restrict__ b_act,
    __half* __restrict__ fH, __half* __restrict__ fL,
    float* __restrict__ out_act)
{
    int m = blockIdx.x, tid = threadIdx.x;
    int c = tid * 4;
    int lane = tid & 31, wid = tid >> 5;
    __shared__ float sred[48];

    float4 v = *(const float4*)(b_emb + c);
#pragma unroll
    for (int s = 0; s < KSPLIT; ++s) {
        float4 p = *(const float4*)(partial + ((size_t)s * R_TOT + m) * NFB + c);
        v.x += p.x; v.y += p.y; v.z += p.z; v.w += p.w;
    }
    float S = v.x + v.y + v.z + v.w;
    float SS = v.x * v.x + v.y * v.y + v.z * v.z + v.w * v.w;
#pragma unroll
    for (int o = 16; o; o >>= 1) {
        S  += __shfl_down_sync(0xffffffffu, S,  o);
        SS += __shfl_down_sync(0xffffffffu, SS, o);
    }
    if (lane == 0) { sred[wid * 2] = S; sred[wid * 2 + 1] = SS; }
    __syncthreads();
    float tS = 0.f, tSS = 0.f;
#pragma unroll
    for (int w = 0; w < 8; ++w) { tS += sred[w * 2]; tSS += sred[w * 2 + 1]; }
    float mean = tS * (1.0f / NFB);
    float var  = tSS * (1.0f / NFB) - mean * mean;
    float rstd = rsqrtf(var + 1e-5f);

    float4 g = *(const float4*)(ln_g + c);
    float4 bb = *(const float4*)(ln_b + c);
    float f0 = fmaxf((v.x - mean) * rstd * g.x + bb.x, 0.f);
    float f1 = fmaxf((v.y - mean) * rstd * g.y + bb.y, 0.f);
    float f2 = fmaxf((v.z - mean) * rstd * g.z + bb.z, 0.f);
    float f3 = fmaxf((v.w - mean) * rstd * g.w + bb.w, 0.f);

    size_t fo = (size_t)m * NFB + c;
    __half h, l;
    split_h(f0, h, l); fH[fo + 0] = h; fL[fo + 0] = l;
    split_h(f1, h, l); fH[fo + 1] = h; fL[fo + 1] = l;
    split_h(f2, h, l); fH[fo + 2] = h; fL[fo + 2] = l;
    split_h(f3, h, l); fH[fo + 3] = h; fL[fo + 3] = l;

    float a[NA];
#pragma unroll
    for (int o = 0; o < NA; ++o) {
        float4 w = *(const float4*)(W_act + (size_t)o * NFB + c);
        a[o] = f0 * w.x + f1 * w.y + f2 * w.z + f3 * w.w;
    }
    __syncthreads();
#pragma unroll
    for (int o = 0; o < NA; ++o) {
#pragma unroll
        for (int s = 16; s; s >>= 1) a[o] += __shfl_down_sync(0xffffffffu, a[o], s);
        if (lane == 0) sred[wid * NA + o] = a[o];
    }
    __syncthreads();
    if (tid < NA) {
        float s = 0.f;
#pragma unroll
        for (int w = 0; w < 8; ++w) s += sred[w * NA + tid];
        out_act[m * NA + tid] = s + b_act[tid];
    }
}

// =====================================================================
// pairwise interaction from U/V (UV layout [208][2048], V at col 1024)
// =====================================================================
__global__ __launch_bounds__(256) void pair_kernel(
    const float* __restrict__ UV, const float* __restrict__ b_i1,
    const float* __restrict__ W_i2, const float* __restrict__ b_i2,
    float* __restrict__ out)
{
    int p = blockIdx.x;
    int b = p / NPAIR_B, q = p % NPAIR_B;
    int i = q / (MAXN - 1), jj = q % (MAXN - 1);
    int j = jj + (jj >= i ? 1 : 0);
    const float* U = UV + (size_t)(b * MAXN + i) * (2 * NFB);
    const float* V = UV + (size_t)(b * MAXN + j) * (2 * NFB) + NFB;

    int tid = threadIdx.x, lane = tid & 31, wid = tid >> 5;
    int c = tid * 4;
    __shared__ float sred[16];

    float4 u  = *(const float4*)(U + c);
    float4 v  = *(const float4*)(V + c);
    float4 bi = *(const float4*)(b_i1 + c);
    float4 w0 = *(const float4*)(W_i2 + c);
    float4 w1 = *(const float4*)(W_i2 + NFB + c);

    float t0 = fmaxf(u.x + v.x + bi.x, 0.f);
    float t1 = fmaxf(u.y + v.y + bi.y, 0.f);
    float t2 = fmaxf(u.z + v.z + bi.z, 0.f);
    float t3 = fmaxf(u.w + v.w + bi.w, 0.f);
    float a0 = t0 * w0.x + t1 * w0.y + t2 * w0.z + t3 * w0.w;
    float a1 = t0 * w1.x + t1 * w1.y + t2 * w1.z + t3 * w1.w;
#pragma unroll
    for (int s = 16; s; s >>= 1) {
        a0 += __shfl_down_sync(0xffffffffu, a0, s);
        a1 += __shfl_down_sync(0xffffffffu, a1, s);
    }
    if (lane == 0) { sred[wid * 2] = a0; sred[wid * 2 + 1] = a1; }
    __syncthreads();
    if (tid < 2) {
        float s = 0.f;
#pragma unroll
        for (int w = 0; w < 8; ++w) s += sred[w * 2 + tid];
        out[p * 2 + tid] = s + b_i2[tid];
    }
}

// =====================================================================
// launch
// =====================================================================
extern "C" void kernel_launch(void* const* d_in, const int* in_sizes, int n_in,
                              void* d_out, int out_size)
{
    const float* features = (const float*)d_in[0];
    const float* boxes    = (const float*)d_in[1];
    const float* W_emb = (const float*)d_in[3];
    const float* b_emb = (const float*)d_in[4];
    const float* ln_g  = (const float*)d_in[5];
    const float* ln_b  = (const float*)d_in[6];
    const float* W_act = (const float*)d_in[7];
    const float* b_act = (const float*)d_in[8];
    const float* W_i1  = (const float*)d_in[9];
    const float* b_i1  = (const float*)d_in[10];
    const float* W_i2  = (const float*)d_in[11];
    const float* b_i2  = (const float*)d_in[12];
    float* out = (float*)d_out;

    void *aeh, *ael, *be, *bu, *fh, *fl, *pp, *uvp;
    cudaGetSymbolAddress(&aeh, g_Ae_h); cudaGetSymbolAddress(&ael, g_Ae_l);
    cudaGetSymbolAddress(&be, g_Be);    cudaGetSymbolAddress(&bu, g_Bu);
    cudaGetSymbolAddress(&fh, g_f_h);   cudaGetSymbolAddress(&fl, g_f_l);
    cudaGetSymbolAddress(&pp, g_part);  cudaGetSymbolAddress(&uvp, g_UV);

    static int smem_set = 0;
    if (!smem_set) {
        cudaFuncSetAttribute(hmma_gemm, cudaFuncAttributeMaxDynamicSharedMemorySize, SMEM_DYN);
        smem_set = 1;
    }

    // operand prep
    conv_wemb<<<dim3(KPAD_E / 2048, NFB), 256>>>(W_emb, (__half*)be);
    conv_wi1 <<<2 * NFB, 128>>>(W_i1, (__half*)bu);
    roi_align_kernel<<<dim3(D_CH / 32, R_TOT), 256>>>(features, boxes,
                                                      (__half*)aeh, (__half*)ael);

    // embedding GEMM: [208 x 26624] x [1024 x 26624]^T, split-K=8
    hmma_gemm<<<dim3(NFB / 128, 4, KSPLIT), 256, SMEM_DYN>>>(
        (const __half*)aeh, (const __half*)ael, (const __half*)be,
        KPAD_E, KT_E, (float*)pp, (long)R_TOT * NFB, NFB, R_TOT);

    // reduce + LN + ReLU + action head
    ln_act_kernel<<<R_TOT, 256>>>((const float*)pp, b_emb, ln_g, ln_b, W_act, b_act,
                                  (__half*)fh, (__half*)fl, out);

    // UV GEMM: [208 x 1024] x [2048 x 1024]^T -> UV [208][2048]
    hmma_gemm<<<dim3(2 * NFB / 128, 4, 1), 256, SMEM_DYN>>>(
        (const __half*)fh, (const __half*)fl, (const __half*)bu,
        KPAD_U, KT_U, (float*)uvp, 0L, 2 * NFB, R_TOT);

    // pairwise combine + interaction head
    pair_kernel<<<NPAIR, 256>>>((const float*)uvp, b_i1, W_i2, b_i2, out + R_TOT * NA);
}

// round 5
// speedup vs baseline: 4.4761x; 1.0332x over previous
#include <cuda_runtime.h>
#include <cuda_fp16.h>
#include <cstdint>

// ---------------- problem constants ----------------
#define BT    16
#define D_CH  1056
#define OH    57
#define OW    87
#define MAXN  13
#define KK    5
#define NFB   1024
#define NA    6
#define R_TOT 208
#define KDIM  26400
#define KPAD_E 26624              // 832 * 32
#define KSPLIT 16
#define KT_E   (KPAD_E/32/KSPLIT) // 52 k-chunks (of 32) per split
#define KPAD_U 1024
#define KT_U   (KPAD_U/32)        // 32
#define NPAIR_B 156
#define NPAIR   2496
#define MROWS 256

// ---------------- scratch (device globals; zero-initialized) ----------------
__device__ __align__(16) __half g_Ae_h[MROWS * KPAD_E];
__device__ __align__(16) __half g_Ae_l[MROWS * KPAD_E];
__device__ __align__(16) __half g_Be  [NFB * KPAD_E];
__device__ __align__(16) __half g_Bu  [2 * NFB * KPAD_U];
__device__ __align__(16) __half g_f_h [MROWS * NFB];
__device__ __align__(16) __half g_f_l [MROWS * NFB];
__device__ float g_part[KSPLIT * R_TOT * NFB];
__device__ float g_UV  [R_TOT * 2 * NFB];

// ---------------- helpers ----------------
__device__ __forceinline__ uint32_t smem_u32(const void* p) {
    uint32_t a;
    asm("{ .reg .u64 t; cvta.to.shared.u64 t, %1; cvt.u32.u64 %0, t; }"
        : "=r"(a) : "l"(p));
    return a;
}
__device__ __forceinline__ void cp16(uint32_t dst, const void* src) {
    asm volatile("cp.async.cg.shared.global [%0], [%1], 16;" :: "r"(dst), "l"(src));
}
#define CP_COMMIT() asm volatile("cp.async.commit_group;" ::: "memory")

#define LDM4(R, addr) \
    asm volatile("ldmatrix.sync.aligned.m8n8.x4.shared.b16 {%0,%1,%2,%3}, [%4];" \
        : "=r"((R)[0]), "=r"((R)[1]), "=r"((R)[2]), "=r"((R)[3]) : "r"(addr))

#define MMA(D, A, B0, B1) \
    asm volatile("mma.sync.aligned.m16n8k16.row.col.f32.f16.f16.f32 " \
        "{%0,%1,%2,%3}, {%4,%5,%6,%7}, {%8,%9}, {%0,%1,%2,%3};" \
        : "+f"((D)[0]), "+f"((D)[1]), "+f"((D)[2]), "+f"((D)[3]) \
        : "r"((A)[0]), "r"((A)[1]), "r"((A)[2]), "r"((A)[3]), "r"(B0), "r"(B1))

__device__ __forceinline__ void split_h(float x, __half& h, __half& l) {
    h = __float2half_rn(x);
    l = __float2half_rn(x - __half2float(h));
}

// =====================================================================
// converters (vectorized: 8 elems/thread, 16B stores)
// =====================================================================
__global__ __launch_bounds__(256) void conv_wemb(
    const float* __restrict__ W, __half* __restrict__ o)
{
    int f = blockIdx.y;
    int k0 = (blockIdx.x * 256 + threadIdx.x) * 8;   // grid.x = 13 -> k0 < 26624
    __half h[8];
    const float* src = W + (size_t)f * KDIM + k0;
    if (k0 + 8 <= KDIM) {
        float4 v0 = *(const float4*)src;
        float4 v1 = *(const float4*)(src + 4);
        h[0] = __float2half_rn(v0.x); h[1] = __float2half_rn(v0.y);
        h[2] = __float2half_rn(v0.z); h[3] = __float2half_rn(v0.w);
        h[4] = __float2half_rn(v1.x); h[5] = __float2half_rn(v1.y);
        h[6] = __float2half_rn(v1.z); h[7] = __float2half_rn(v1.w);
    } else {
#pragma unroll
        for (int i = 0; i < 8; ++i)
            h[i] = (k0 + i < KDIM) ? __float2half_rn(src[i]) : __ushort_as_half(0);
    }
    *(uint4*)(o + (size_t)f * KPAD_E + k0) = *(const uint4*)h;
}

__global__ __launch_bounds__(128) void conv_wi1(
    const float* __restrict__ W, __half* __restrict__ o)
{
    int f = blockIdx.x;                              // 0..2047
    int k0 = threadIdx.x * 8;                        // 0..1016
    const float* src = (f < NFB) ? W + (size_t)f * (2 * NFB) + k0
                                 : W + (size_t)(f - NFB) * (2 * NFB) + NFB + k0;
    float4 v0 = *(const float4*)src;
    float4 v1 = *(const float4*)(src + 4);
    __half h[8];
    h[0] = __float2half_rn(v0.x); h[1] = __float2half_rn(v0.y);
    h[2] = __float2half_rn(v0.z); h[3] = __float2half_rn(v0.w);
    h[4] = __float2half_rn(v1.x); h[5] = __float2half_rn(v1.y);
    h[6] = __float2half_rn(v1.z); h[7] = __float2half_rn(v1.w);
    *(uint4*)(o + (size_t)f * KPAD_U + k0) = *(const uint4*)h;
}

// =====================================================================
// ROI align -> fp16 hi/lo A operand (+ pad-zero fold on blockIdx.x==0)
// =====================================================================
__global__ __launch_bounds__(256) void roi_align_kernel(
    const float* __restrict__ feat, const float* __restrict__ boxes,
    __half* __restrict__ ah, __half* __restrict__ al)
{
    int r  = blockIdx.y;
    int d0 = blockIdx.x * 32;
    int b  = r / MAXN;
    const float* bx = boxes + r * 4;
    float x1 = bx[0], y1 = bx[1], x2 = bx[2], y2 = bx[3];
    float bw = (x2 - x1) * (1.0f / KK);
    float bh = (y2 - y1) * (1.0f / KK);

    int tid = threadIdx.x;
    int dl = tid >> 3, pl = tid & 7;
    const float* fb = feat + (size_t)(b * D_CH + d0 + dl) * (OH * OW);

    __shared__ float tile[32][25];
    for (int p = pl; p < 25; p += 8) {
        int iy = p / 5, jx = p % 5;
        float xs = x1 + (jx + 0.5f) * bw;
        float ys = y1 + (iy + 0.5f) * bh;
        float x0f = floorf(xs), y0f = floorf(ys);
        float lx = xs - x0f, ly = ys - y0f;
        int x0 = (int)x0f, y0 = (int)y0f;
        int x0i = min(max(x0, 0), OW - 1);
        int x1i = min(max(x0 + 1, 0), OW - 1);
        int y0i = min(max(y0, 0), OH - 1);
        int y1i = min(max(y0 + 1, 0), OH - 1);
        float v00 = fb[y0i * OW + x0i], v01 = fb[y0i * OW + x1i];
        float v10 = fb[y1i * OW + x0i], v11 = fb[y1i * OW + x1i];
        float wy0 = 1.f - ly, wx0 = 1.f - lx;
        tile[dl][p] = v00 * wy0 * wx0 + v01 * wy0 * lx
                    + v10 * ly  * wx0 + v11 * ly  * lx;
    }
    __syncthreads();
    size_t base = (size_t)r * KPAD_E + d0 * 25;
    const float* src = &tile[0][0];
    for (int t = tid; t < 800; t += 256) {
        __half h, l; split_h(src[t], h, l);
        ah[base + t] = h; al[base + t] = l;
    }
    // fold pad-zero: cols [KDIM, KPAD_E) of row r (224 halves = 28 uint4)
    if (blockIdx.x == 0 && tid < 28) {
        uint4 z = make_uint4(0, 0, 0, 0);
        *(uint4*)(ah + (size_t)r * KPAD_E + KDIM + tid * 8) = z;
        *(uint4*)(al + (size_t)r * KPAD_E + KDIM + tid * 8) = z;
    }
}

// =====================================================================
// HMMA fp16 split-2 GEMM: C[z] = (Ah + Al) * B^T   (B pre-rounded fp16)
//   block tile 64(M) x 128(N) x 32(K), 8 warps (2M x 4N),
//   3-stage cp.async pipeline, row stride 80B, dead-M-row skip
// =====================================================================
#define ROWB 80
#define AH_OFF 0
#define AL_OFF (64 * ROWB)              // 5120
#define B_OFF  (2 * 64 * ROWB)          // 10240
#define STAGE_SZ (B_OFF + 128 * ROWB)   // 20480
#define NSTAGE 3
#define SMEM_DYN (NSTAGE * STAGE_SZ)    // 61440

__global__ __launch_bounds__(256, 3) void hmma_gemm(
    const __half* __restrict__ Ah, const __half* __restrict__ Al,
    const __half* __restrict__ B,
    int kPad, int kTiles, float* __restrict__ C, long cZstride,
    int Nld, int Mreal)
{
    extern __shared__ char smraw[];
    const uint32_t sm = smem_u32(smraw);
    const int tid = threadIdx.x;
    const int lane = tid & 31, wid = tid >> 5;
    const int wm = wid & 1, wn = wid >> 1;          // 2 M-warps x 4 N-warps
    const int n0 = blockIdx.x * 128, m0 = blockIdx.y * 64, z = blockIdx.z;
    const long k00 = (long)z * kTiles * 32;
    C += (long)z * cZstride;

    // per-warp activity (M blocks of 16; Mreal is a multiple of 16)
    const bool act0 = (m0 + wm * 32)      < Mreal;
    const bool act1 = (m0 + wm * 32 + 16) < Mreal;

    // ---- load maps
    const int lrow = tid >> 2, lc = tid & 3;        // lrow 0..63, lc 0..3
    const __half* aHp = Ah + (size_t)(m0 + lrow) * kPad + lc * 8;
    const __half* aLp = Al + (size_t)(m0 + lrow) * kPad + lc * 8;
    const __half* bP0 = B + (size_t)(n0 + lrow) * kPad + lc * 8;
    const __half* bP1 = B + (size_t)(n0 + 64 + lrow) * kPad + lc * 8;
    const uint32_t aDst = lrow * ROWB + lc * 16;
    const uint32_t bDst0 = lrow * ROWB + lc * 16;
    const uint32_t bDst1 = (64 + lrow) * ROWB + lc * 16;

    // ---- ldmatrix per-lane bases
    const uint32_t aLdm = sm + (wm * 32 + (lane & 15)) * ROWB + (lane >> 4) * 16;
    const uint32_t bLdm = sm + (wn * 32 + (lane & 15)) * ROWB + (lane >> 4) * 16;

    float d[2][4][4];
#pragma unroll
    for (int mi = 0; mi < 2; ++mi)
#pragma unroll
        for (int ni = 0; ni < 4; ++ni)
#pragma unroll
            for (int q = 0; q < 4; ++q) d[mi][ni][q] = 0.f;

    auto load_stage = [&](int s, int kt) {
        long ke = k00 + (long)kt * 32;
        uint32_t st = sm + s * STAGE_SZ;
        cp16(st + AH_OFF + aDst, aHp + ke);
        cp16(st + AL_OFF + aDst, aLp + ke);
        cp16(st + B_OFF + bDst0, bP0 + ke);
        cp16(st + B_OFF + bDst1, bP1 + ke);
        CP_COMMIT();
    };

    // prologue: fill 2 of 3 stages
    load_stage(0, 0);
    load_stage(1, 1);

    int s = 0;
    for (int kt = 0; kt < kTiles; ++kt) {
        // issue load for kt+2 into the stage freed at end of iter kt-1,
        // then wait until the group for kt has landed
        if (kt + 2 < kTiles) {
            int s2 = s + 2; if (s2 >= NSTAGE) s2 -= NSTAGE;
            load_stage(s2, kt + 2);
            asm volatile("cp.async.wait_group 2;" ::: "memory");
        } else if (kt + 1 < kTiles) {
            asm volatile("cp.async.wait_group 1;" ::: "memory");
        } else {
            asm volatile("cp.async.wait_group 0;" ::: "memory");
        }
        __syncthreads();

        uint32_t stA = aLdm + s * STAGE_SZ;
        uint32_t stB = bLdm + s * STAGE_SZ;
#pragma unroll
        for (int ks = 0; ks < 2; ++ks) {
            uint32_t ah[2][4], al_[2][4], b[2][4];
#pragma unroll
            for (int pr = 0; pr < 2; ++pr)
                LDM4(b[pr], stB + B_OFF + pr * (16 * ROWB) + ks * 32);
            if (act0) {
                LDM4(ah[0],  stA + AH_OFF + ks * 32);
                LDM4(al_[0], stA + AL_OFF + ks * 32);
            }
            if (act1) {
                LDM4(ah[1],  stA + AH_OFF + 16 * ROWB + ks * 32);
                LDM4(al_[1], stA + AL_OFF + 16 * ROWB + ks * 32);
            }
#pragma unroll
            for (int mi = 0; mi < 2; ++mi) {
                if (mi == 0 ? !act0 : !act1) continue;
#pragma unroll
                for (int ni = 0; ni < 4; ++ni) {
                    int pr = ni >> 1, hi = ni & 1;
                    MMA(d[mi][ni], ah[mi],  b[pr][hi], b[pr][hi + 2]);
                    MMA(d[mi][ni], al_[mi], b[pr][hi], b[pr][hi + 2]);
                }
            }
        }
        __syncthreads();
        if (++s == NSTAGE) s = 0;
    }

    // ---- epilogue
#pragma unroll
    for (int mi = 0; mi < 2; ++mi) {
        int r0 = m0 + wm * 32 + mi * 16 + (lane >> 2);
        int r1 = r0 + 8;
#pragma unroll
        for (int ni = 0; ni < 4; ++ni) {
            int col = n0 + wn * 32 + ni * 8 + (lane & 3) * 2;
            if (r0 < Mreal)
                *(float2*)(C + (size_t)r0 * Nld + col) = make_float2(d[mi][ni][0], d[mi][ni][1]);
            if (r1 < Mreal)
                *(float2*)(C + (size_t)r1 * Nld + col) = make_float2(d[mi][ni][2], d[mi][ni][3]);
        }
    }
}

// =====================================================================
// split-K reduce + bias + LayerNorm + ReLU + action head; emits fp16 hi/lo
// =====================================================================
__global__ __launch_bounds__(256) void ln_act_kernel(
    const float* __restrict__ partial, const float* __restrict__ b_emb,
    const float* __restrict__ ln_g, const float* __restrict__ ln_b,
    const float* __restrict__ W_act, const float* __restrict__ b_act,
    __half* __restrict__ fH, __half* __restrict__ fL,
    float* __restrict__ out_act)
{
    int m = blockIdx.x, tid = threadIdx.x;
    int c = tid * 4;
    int lane = tid & 31, wid = tid >> 5;
    __shared__ float sred[48];

    float4 v = *(const float4*)(b_emb + c);
#pragma unroll
    for (int s = 0; s < KSPLIT; ++s) {
        float4 p = *(const float4*)(partial + ((size_t)s * R_TOT + m) * NFB + c);
        v.x += p.x; v.y += p.y; v.z += p.z; v.w += p.w;
    }
    float S = v.x + v.y + v.z + v.w;
    float SS = v.x * v.x + v.y * v.y + v.z * v.z + v.w * v.w;
#pragma unroll
    for (int o = 16; o; o >>= 1) {
        S  += __shfl_down_sync(0xffffffffu, S,  o);
        SS += __shfl_down_sync(0xffffffffu, SS, o);
    }
    if (lane == 0) { sred[wid * 2] = S; sred[wid * 2 + 1] = SS; }
    __syncthreads();
    float tS = 0.f, tSS = 0.f;
#pragma unroll
    for (int w = 0; w < 8; ++w) { tS += sred[w * 2]; tSS += sred[w * 2 + 1]; }
    float mean = tS * (1.0f / NFB);
    float var  = tSS * (1.0f / NFB) - mean * mean;
    float rstd = rsqrtf(var + 1e-5f);

    float4 g = *(const float4*)(ln_g + c);
    float4 bb = *(const float4*)(ln_b + c);
    float f0 = fmaxf((v.x - mean) * rstd * g.x + bb.x, 0.f);
    float f1 = fmaxf((v.y - mean) * rstd * g.y + bb.y, 0.f);
    float f2 = fmaxf((v.z - mean) * rstd * g.z + bb.z, 0.f);
    float f3 = fmaxf((v.w - mean) * rstd * g.w + bb.w, 0.f);

    size_t fo = (size_t)m * NFB + c;
    __half h, l;
    split_h(f0, h, l); fH[fo + 0] = h; fL[fo + 0] = l;
    split_h(f1, h, l); fH[fo + 1] = h; fL[fo + 1] = l;
    split_h(f2, h, l); fH[fo + 2] = h; fL[fo + 2] = l;
    split_h(f3, h, l); fH[fo + 3] = h; fL[fo + 3] = l;

    float a[NA];
#pragma unroll
    for (int o = 0; o < NA; ++o) {
        float4 w = *(const float4*)(W_act + (size_t)o * NFB + c);
        a[o] = f0 * w.x + f1 * w.y + f2 * w.z + f3 * w.w;
    }
    __syncthreads();
#pragma unroll
    for (int o = 0; o < NA; ++o) {
#pragma unroll
        for (int s = 16; s; s >>= 1) a[o] += __shfl_down_sync(0xffffffffu, a[o], s);
        if (lane == 0) sred[wid * NA + o] = a[o];
    }
    __syncthreads();
    if (tid < NA) {
        float s = 0.f;
#pragma unroll
        for (int w = 0; w < 8; ++w) s += sred[w * NA + tid];
        out_act[m * NA + tid] = s + b_act[tid];
    }
}

// =====================================================================
// pairwise interaction from U/V (UV layout [208][2048], V at col 1024)
// =====================================================================
__global__ __launch_bounds__(256) void pair_kernel(
    const float* __restrict__ UV, const float* __restrict__ b_i1,
    const float* __restrict__ W_i2, const float* __restrict__ b_i2,
    float* __restrict__ out)
{
    int p = blockIdx.x;
    int b = p / NPAIR_B, q = p % NPAIR_B;
    int i = q / (MAXN - 1), jj = q % (MAXN - 1);
    int j = jj + (jj >= i ? 1 : 0);
    const float* U = UV + (size_t)(b * MAXN + i) * (2 * NFB);
    const float* V = UV + (size_t)(b * MAXN + j) * (2 * NFB) + NFB;

    int tid = threadIdx.x, lane = tid & 31, wid = tid >> 5;
    int c = tid * 4;
    __shared__ float sred[16];

    float4 u  = *(const float4*)(U + c);
    float4 v  = *(const float4*)(V + c);
    float4 bi = *(const float4*)(b_i1 + c);
    float4 w0 = *(const float4*)(W_i2 + c);
    float4 w1 = *(const float4*)(W_i2 + NFB + c);

    float t0 = fmaxf(u.x + v.x + bi.x, 0.f);
    float t1 = fmaxf(u.y + v.y + bi.y, 0.f);
    float t2 = fmaxf(u.z + v.z + bi.z, 0.f);
    float t3 = fmaxf(u.w + v.w + bi.w, 0.f);
    float a0 = t0 * w0.x + t1 * w0.y + t2 * w0.z + t3 * w0.w;
    float a1 = t0 * w1.x + t1 * w1.y + t2 * w1.z + t3 * w1.w;
#pragma unroll
    for (int s = 16; s; s >>= 1) {
        a0 += __shfl_down_sync(0xffffffffu, a0, s);
        a1 += __shfl_down_sync(0xffffffffu, a1, s);
    }
    if (lane == 0) { sred[wid * 2] = a0; sred[wid * 2 + 1] = a1; }
    __syncthreads();
    if (tid < 2) {
        float s = 0.f;
#pragma unroll
        for (int w = 0; w < 8; ++w) s += sred[w * 2 + tid];
        out[p * 2 + tid] = s + b_i2[tid];
    }
}

// =====================================================================
// launch
// =====================================================================
extern "C" void kernel_launch(void* const* d_in, const int* in_sizes, int n_in,
                              void* d_out, int out_size)
{
    const float* features = (const float*)d_in[0];
    const float* boxes    = (const float*)d_in[1];
    const float* W_emb = (const float*)d_in[3];
    const float* b_emb = (const float*)d_in[4];
    const float* ln_g  = (const float*)d_in[5];
    const float* ln_b  = (const float*)d_in[6];
    const float* W_act = (const float*)d_in[7];
    const float* b_act = (const float*)d_in[8];
    const float* W_i1  = (const float*)d_in[9];
    const float* b_i1  = (const float*)d_in[10];
    const float* W_i2  = (const float*)d_in[11];
    const float* b_i2  = (const float*)d_in[12];
    float* out = (float*)d_out;

    void *aeh, *ael, *be, *bu, *fh, *fl, *pp, *uvp;
    cudaGetSymbolAddress(&aeh, g_Ae_h); cudaGetSymbolAddress(&ael, g_Ae_l);
    cudaGetSymbolAddress(&be, g_Be);    cudaGetSymbolAddress(&bu, g_Bu);
    cudaGetSymbolAddress(&fh, g_f_h);   cudaGetSymbolAddress(&fl, g_f_l);
    cudaGetSymbolAddress(&pp, g_part);  cudaGetSymbolAddress(&uvp, g_UV);

    static int smem_set = 0;
    if (!smem_set) {
        cudaFuncSetAttribute(hmma_gemm, cudaFuncAttributeMaxDynamicSharedMemorySize, SMEM_DYN);
        smem_set = 1;
    }

    // operand prep
    conv_wemb<<<dim3(KPAD_E / 2048, NFB), 256>>>(W_emb, (__half*)be);
    conv_wi1 <<<2 * NFB, 128>>>(W_i1, (__half*)bu);
    roi_align_kernel<<<dim3(D_CH / 32, R_TOT), 256>>>(features, boxes,
                                                      (__half*)aeh, (__half*)ael);

    // embedding GEMM: [208 x 26624] x [1024 x 26624]^T, split-K=16
    hmma_gemm<<<dim3(NFB / 128, 4, KSPLIT), 256, SMEM_DYN>>>(
        (const __half*)aeh, (const __half*)ael, (const __half*)be,
        KPAD_E, KT_E, (float*)pp, (long)R_TOT * NFB, NFB, R_TOT);

    // reduce + LN + ReLU + action head
    ln_act_kernel<<<R_TOT, 256>>>((const float*)pp, b_emb, ln_g, ln_b, W_act, b_act,
                                  (__half*)fh, (__half*)fl, out);

    // UV GEMM: [208 x 1024] x [2048 x 1024]^T -> UV [208][2048]
    hmma_gemm<<<dim3(2 * NFB / 128, 4, 1), 256, SMEM_DYN>>>(
        (const __half*)fh, (const __half*)fl, (const __half*)bu,
        KPAD_U, KT_U, (float*)uvp, 0L, 2 * NFB, R_TOT);

    // pairwise combine + interaction head
    pair_kernel<<<NPAIR, 256>>>((const float*)uvp, b_i1, W_i2, b_i2, out + R_TOT * NA);
}

// round 6
// speedup vs baseline: 4.8009x; 1.0726x over previous
#include <cuda_runtime.h>
#include <cuda_fp16.h>
#include <cstdint>

// ---------------- problem constants ----------------
#define BT    16
#define D_CH  1056
#define OH    57
#define OW    87
#define MAXN  13
#define KK    5
#define NFB   1024
#define NA    6
#define R_TOT 208
#define KDIM  26400
#define KPAD_E 26624              // 832 * 32
#define KSPLIT 32
#define KT_E   (KPAD_E/32/KSPLIT) // 26 k-chunks (of 32) per split
#define KPAD_U 1024
#define KSPLIT_U 4
#define KT_U   (KPAD_U/32/KSPLIT_U) // 8
#define NPAIR_B 156
#define NPAIR   2496
#define MROWS 256

// ---------------- scratch (device globals; zero-initialized) ----------------
__device__ __align__(16) __half g_Ae_h[MROWS * KPAD_E];
__device__ __align__(16) __half g_Ae_l[MROWS * KPAD_E];
__device__ __align__(16) __half g_Be  [NFB * KPAD_E];
__device__ __align__(16) __half g_Bu  [2 * NFB * KPAD_U];
__device__ __align__(16) __half g_f_h [MROWS * NFB];
__device__ __align__(16) __half g_f_l [MROWS * NFB];
__device__ float g_part[KSPLIT * R_TOT * NFB];
__device__ float g_UVp [KSPLIT_U * R_TOT * 2 * NFB];
__device__ float g_UV  [R_TOT * 2 * NFB];

// ---------------- helpers ----------------
__device__ __forceinline__ uint32_t smem_u32(const void* p) {
    uint32_t a;
    asm("{ .reg .u64 t; cvta.to.shared.u64 t, %1; cvt.u32.u64 %0, t; }"
        : "=r"(a) : "l"(p));
    return a;
}
__device__ __forceinline__ void cp16(uint32_t dst, const void* src) {
    asm volatile("cp.async.cg.shared.global [%0], [%1], 16;" :: "r"(dst), "l"(src));
}
#define CP_COMMIT() asm volatile("cp.async.commit_group;" ::: "memory")

#define LDM4(R, addr) \
    asm volatile("ldmatrix.sync.aligned.m8n8.x4.shared.b16 {%0,%1,%2,%3}, [%4];" \
        : "=r"((R)[0]), "=r"((R)[1]), "=r"((R)[2]), "=r"((R)[3]) : "r"(addr))

#define MMA(D, A, B0, B1) \
    asm volatile("mma.sync.aligned.m16n8k16.row.col.f32.f16.f16.f32 " \
        "{%0,%1,%2,%3}, {%4,%5,%6,%7}, {%8,%9}, {%0,%1,%2,%3};" \
        : "+f"((D)[0]), "+f"((D)[1]), "+f"((D)[2]), "+f"((D)[3]) \
        : "r"((A)[0]), "r"((A)[1]), "r"((A)[2]), "r"((A)[3]), "r"(B0), "r"(B1))

__device__ __forceinline__ void split_h(float x, __half& h, __half& l) {
    h = __float2half_rn(x);
    l = __float2half_rn(x - __half2float(h));
}

// =====================================================================
// converters (vectorized: 8 elems/thread, 16B stores)
// =====================================================================
__global__ __launch_bounds__(256) void conv_wemb(
    const float* __restrict__ W, __half* __restrict__ o)
{
    int f = blockIdx.y;
    int k0 = (blockIdx.x * 256 + threadIdx.x) * 8;
    __half h[8];
    const float* src = W + (size_t)f * KDIM + k0;
    if (k0 + 8 <= KDIM) {
        float4 v0 = *(const float4*)src;
        float4 v1 = *(const float4*)(src + 4);
        h[0] = __float2half_rn(v0.x); h[1] = __float2half_rn(v0.y);
        h[2] = __float2half_rn(v0.z); h[3] = __float2half_rn(v0.w);
        h[4] = __float2half_rn(v1.x); h[5] = __float2half_rn(v1.y);
        h[6] = __float2half_rn(v1.z); h[7] = __float2half_rn(v1.w);
    } else {
#pragma unroll
        for (int i = 0; i < 8; ++i)
            h[i] = (k0 + i < KDIM) ? __float2half_rn(src[i]) : __ushort_as_half(0);
    }
    *(uint4*)(o + (size_t)f * KPAD_E + k0) = *(const uint4*)h;
}

__global__ __launch_bounds__(128) void conv_wi1(
    const float* __restrict__ W, __half* __restrict__ o)
{
    int f = blockIdx.x;
    int k0 = threadIdx.x * 8;
    const float* src = (f < NFB) ? W + (size_t)f * (2 * NFB) + k0
                                 : W + (size_t)(f - NFB) * (2 * NFB) + NFB + k0;
    float4 v0 = *(const float4*)src;
    float4 v1 = *(const float4*)(src + 4);
    __half h[8];
    h[0] = __float2half_rn(v0.x); h[1] = __float2half_rn(v0.y);
    h[2] = __float2half_rn(v0.z); h[3] = __float2half_rn(v0.w);
    h[4] = __float2half_rn(v1.x); h[5] = __float2half_rn(v1.y);
    h[6] = __float2half_rn(v1.z); h[7] = __float2half_rn(v1.w);
    *(uint4*)(o + (size_t)f * KPAD_U + k0) = *(const uint4*)h;
}

// =====================================================================
// ROI align -> fp16 hi/lo A operand (+ pad-zero fold on blockIdx.x==0)
// =====================================================================
__global__ __launch_bounds__(256) void roi_align_kernel(
    const float* __restrict__ feat, const float* __restrict__ boxes,
    __half* __restrict__ ah, __half* __restrict__ al)
{
    int r  = blockIdx.y;
    int d0 = blockIdx.x * 32;
    int b  = r / MAXN;
    const float* bx = boxes + r * 4;
    float x1 = bx[0], y1 = bx[1], x2 = bx[2], y2 = bx[3];
    float bw = (x2 - x1) * (1.0f / KK);
    float bh = (y2 - y1) * (1.0f / KK);

    int tid = threadIdx.x;
    int dl = tid >> 3, pl = tid & 7;
    const float* fb = feat + (size_t)(b * D_CH + d0 + dl) * (OH * OW);

    __shared__ float tile[32][25];
    for (int p = pl; p < 25; p += 8) {
        int iy = p / 5, jx = p % 5;
        float xs = x1 + (jx + 0.5f) * bw;
        float ys = y1 + (iy + 0.5f) * bh;
        float x0f = floorf(xs), y0f = floorf(ys);
        float lx = xs - x0f, ly = ys - y0f;
        int x0 = (int)x0f, y0 = (int)y0f;
        int x0i = min(max(x0, 0), OW - 1);
        int x1i = min(max(x0 + 1, 0), OW - 1);
        int y0i = min(max(y0, 0), OH - 1);
        int y1i = min(max(y0 + 1, 0), OH - 1);
        float v00 = fb[y0i * OW + x0i], v01 = fb[y0i * OW + x1i];
        float v10 = fb[y1i * OW + x0i], v11 = fb[y1i * OW + x1i];
        float wy0 = 1.f - ly, wx0 = 1.f - lx;
        tile[dl][p] = v00 * wy0 * wx0 + v01 * wy0 * lx
                    + v10 * ly  * wx0 + v11 * ly  * lx;
    }
    __syncthreads();
    size_t base = (size_t)r * KPAD_E + d0 * 25;  // 800-aligned offset, even
    const float* src = &tile[0][0];
    for (int t = tid; t < 400; t += 256) {
        float s0 = src[2 * t], s1 = src[2 * t + 1];
        __half h0, l0, h1, l1;
        split_h(s0, h0, l0); split_h(s1, h1, l1);
        *(__half2*)(ah + base + 2 * t) = __halves2half2(h0, h1);
        *(__half2*)(al + base + 2 * t) = __halves2half2(l0, l1);
    }
    // fold pad-zero: cols [KDIM, KPAD_E) of row r (224 halves = 28 uint4)
    if (blockIdx.x == 0 && tid < 28) {
        uint4 z = make_uint4(0, 0, 0, 0);
        *(uint4*)(ah + (size_t)r * KPAD_E + KDIM + tid * 8) = z;
        *(uint4*)(al + (size_t)r * KPAD_E + KDIM + tid * 8) = z;
    }
}

// =====================================================================
// HMMA fp16 split-2 GEMM: C[z] = (Ah + Al) * B^T   (B pre-rounded fp16)
//   block tile 64(M) x 256(N) x 32(K), 8 warps (2M x 4N, warp tile 32x64),
//   3-stage cp.async pipeline, row stride 80B, dead-M-row skip
// =====================================================================
#define ROWB 80
#define AH_OFF 0
#define AL_OFF (64 * ROWB)              // 5120
#define B_OFF  (2 * 64 * ROWB)          // 10240
#define STAGE_SZ (B_OFF + 256 * ROWB)   // 30720
#define NSTAGE 3
#define SMEM_DYN (NSTAGE * STAGE_SZ)    // 92160

__global__ __launch_bounds__(256, 2) void hmma_gemm(
    const __half* __restrict__ Ah, const __half* __restrict__ Al,
    const __half* __restrict__ B,
    int kPad, int kTiles, float* __restrict__ C, long cZstride,
    int Nld, int Mreal)
{
    extern __shared__ char smraw[];
    const uint32_t sm = smem_u32(smraw);
    const int tid = threadIdx.x;
    const int lane = tid & 31, wid = tid >> 5;
    const int wm = wid & 1, wn = wid >> 1;          // 2 M-warps x 4 N-warps
    const int n0 = blockIdx.x * 256, m0 = blockIdx.y * 64, z = blockIdx.z;
    const long k00 = (long)z * kTiles * 32;
    C += (long)z * cZstride;

    // per-warp activity (M blocks of 16; Mreal is a multiple of 16)
    const bool act0 = (m0 + wm * 32)      < Mreal;
    const bool act1 = (m0 + wm * 32 + 16) < Mreal;

    // ---- load maps: A 128 rows (64 hi + 64 lo) = 2 cp16/thr, B 256 rows = 4 cp16/thr
    const int lrow = tid >> 2, lc = tid & 3;        // lrow 0..63, lc 0..3
    const __half* aHp = Ah + (size_t)(m0 + lrow) * kPad + lc * 8;
    const __half* aLp = Al + (size_t)(m0 + lrow) * kPad + lc * 8;
    const __half* bP[4];
#pragma unroll
    for (int p = 0; p < 4; ++p)
        bP[p] = B + (size_t)(n0 + p * 64 + lrow) * kPad + lc * 8;
    const uint32_t aDst = lrow * ROWB + lc * 16;
    const uint32_t bDstBase = lrow * ROWB + lc * 16;

    // ---- ldmatrix per-lane bases
    const uint32_t aLdm = sm + (wm * 32 + (lane & 15)) * ROWB + (lane >> 4) * 16;
    const uint32_t bLdm = sm + B_OFF + (wn * 64 + (lane & 15)) * ROWB + (lane >> 4) * 16;

    float d[2][8][4];
#pragma unroll
    for (int mi = 0; mi < 2; ++mi)
#pragma unroll
        for (int ni = 0; ni < 8; ++ni)
#pragma unroll
            for (int q = 0; q < 4; ++q) d[mi][ni][q] = 0.f;

    auto load_stage = [&](int s, int kt) {
        long ke = k00 + (long)kt * 32;
        uint32_t st = sm + s * STAGE_SZ;
        cp16(st + AH_OFF + aDst, aHp + ke);
        cp16(st + AL_OFF + aDst, aLp + ke);
#pragma unroll
        for (int p = 0; p < 4; ++p)
            cp16(st + B_OFF + bDstBase + p * (64 * ROWB), bP[p] + ke);
        CP_COMMIT();
    };

    // prologue: fill 2 of 3 stages
    load_stage(0, 0);
    load_stage(1, 1);

    int s = 0;
    for (int kt = 0; kt < kTiles; ++kt) {
        if (kt + 2 < kTiles) {
            int s2 = s + 2; if (s2 >= NSTAGE) s2 -= NSTAGE;
            load_stage(s2, kt + 2);
            asm volatile("cp.async.wait_group 2;" ::: "memory");
        } else if (kt + 1 < kTiles) {
            asm volatile("cp.async.wait_group 1;" ::: "memory");
        } else {
            asm volatile("cp.async.wait_group 0;" ::: "memory");
        }
        __syncthreads();

        uint32_t stA = aLdm + s * STAGE_SZ;
        uint32_t stB = bLdm + s * STAGE_SZ;
#pragma unroll
        for (int ks = 0; ks < 2; ++ks) {
            uint32_t ah[2][4], al_[2][4], b[4][4];
#pragma unroll
            for (int pr = 0; pr < 4; ++pr)
                LDM4(b[pr], stB + pr * (16 * ROWB) + ks * 32);
            if (act0) {
                LDM4(ah[0],  stA + AH_OFF + ks * 32);
                LDM4(al_[0], stA + AL_OFF + ks * 32);
            }
            if (act1) {
                LDM4(ah[1],  stA + AH_OFF + 16 * ROWB + ks * 32);
                LDM4(al_[1], stA + AL_OFF + 16 * ROWB + ks * 32);
            }
#pragma unroll
            for (int mi = 0; mi < 2; ++mi) {
                if (mi == 0 ? !act0 : !act1) continue;
#pragma unroll
                for (int ni = 0; ni < 8; ++ni) {
                    int pr = ni >> 1, hi = ni & 1;
                    MMA(d[mi][ni], ah[mi],  b[pr][hi], b[pr][hi + 2]);
                    MMA(d[mi][ni], al_[mi], b[pr][hi], b[pr][hi + 2]);
                }
            }
        }
        __syncthreads();
        if (++s == NSTAGE) s = 0;
    }

    // ---- epilogue
#pragma unroll
    for (int mi = 0; mi < 2; ++mi) {
        int r0 = m0 + wm * 32 + mi * 16 + (lane >> 2);
        int r1 = r0 + 8;
#pragma unroll
        for (int ni = 0; ni < 8; ++ni) {
            int col = n0 + wn * 64 + ni * 8 + (lane & 3) * 2;
            if (r0 < Mreal)
                *(float2*)(C + (size_t)r0 * Nld + col) = make_float2(d[mi][ni][0], d[mi][ni][1]);
            if (r1 < Mreal)
                *(float2*)(C + (size_t)r1 * Nld + col) = make_float2(d[mi][ni][2], d[mi][ni][3]);
        }
    }
}

// =====================================================================
// split-K reduce + bias + LayerNorm + ReLU + action head; emits fp16 hi/lo
// =====================================================================
__global__ __launch_bounds__(256) void ln_act_kernel(
    const float* __restrict__ partial, const float* __restrict__ b_emb,
    const float* __restrict__ ln_g, const float* __restrict__ ln_b,
    const float* __restrict__ W_act, const float* __restrict__ b_act,
    __half* __restrict__ fH, __half* __restrict__ fL,
    float* __restrict__ out_act)
{
    int m = blockIdx.x, tid = threadIdx.x;
    int c = tid * 4;
    int lane = tid & 31, wid = tid >> 5;
    __shared__ float sred[48];

    float4 v = *(const float4*)(b_emb + c);
#pragma unroll
    for (int s = 0; s < KSPLIT; ++s) {
        float4 p = *(const float4*)(partial + ((size_t)s * R_TOT + m) * NFB + c);
        v.x += p.x; v.y += p.y; v.z += p.z; v.w += p.w;
    }
    float S = v.x + v.y + v.z + v.w;
    float SS = v.x * v.x + v.y * v.y + v.z * v.z + v.w * v.w;
#pragma unroll
    for (int o = 16; o; o >>= 1) {
        S  += __shfl_down_sync(0xffffffffu, S,  o);
        SS += __shfl_down_sync(0xffffffffu, SS, o);
    }
    if (lane == 0) { sred[wid * 2] = S; sred[wid * 2 + 1] = SS; }
    __syncthreads();
    float tS = 0.f, tSS = 0.f;
#pragma unroll
    for (int w = 0; w < 8; ++w) { tS += sred[w * 2]; tSS += sred[w * 2 + 1]; }
    float mean = tS * (1.0f / NFB);
    float var  = tSS * (1.0f / NFB) - mean * mean;
    float rstd = rsqrtf(var + 1e-5f);

    float4 g = *(const float4*)(ln_g + c);
    float4 bb = *(const float4*)(ln_b + c);
    float f0 = fmaxf((v.x - mean) * rstd * g.x + bb.x, 0.f);
    float f1 = fmaxf((v.y - mean) * rstd * g.y + bb.y, 0.f);
    float f2 = fmaxf((v.z - mean) * rstd * g.z + bb.z, 0.f);
    float f3 = fmaxf((v.w - mean) * rstd * g.w + bb.w, 0.f);

    size_t fo = (size_t)m * NFB + c;
    __half h, l;
    split_h(f0, h, l); fH[fo + 0] = h; fL[fo + 0] = l;
    split_h(f1, h, l); fH[fo + 1] = h; fL[fo + 1] = l;
    split_h(f2, h, l); fH[fo + 2] = h; fL[fo + 2] = l;
    split_h(f3, h, l); fH[fo + 3] = h; fL[fo + 3] = l;

    float a[NA];
#pragma unroll
    for (int o = 0; o < NA; ++o) {
        float4 w = *(const float4*)(W_act + (size_t)o * NFB + c);
        a[o] = f0 * w.x + f1 * w.y + f2 * w.z + f3 * w.w;
    }
    __syncthreads();
#pragma unroll
    for (int o = 0; o < NA; ++o) {
#pragma unroll
        for (int s = 16; s; s >>= 1) a[o] += __shfl_down_sync(0xffffffffu, a[o], s);
        if (lane == 0) sred[wid * NA + o] = a[o];
    }
    __syncthreads();
    if (tid < NA) {
        float s = 0.f;
#pragma unroll
        for (int w = 0; w < 8; ++w) s += sred[w * NA + tid];
        out_act[m * NA + tid] = s + b_act[tid];
    }
}

// =====================================================================
// UV split-K reduce: g_UV = sum_s g_UVp[s]
// =====================================================================
__global__ __launch_bounds__(256) void uv_reduce(
    const float* __restrict__ part, float* __restrict__ out)
{
    size_t i = ((size_t)blockIdx.x * 256 + threadIdx.x) * 4;  // over 208*2048
    float4 v = *(const float4*)(part + i);
#pragma unroll
    for (int s = 1; s < KSPLIT_U; ++s) {
        float4 p = *(const float4*)(part + (size_t)s * R_TOT * 2 * NFB + i);
        v.x += p.x; v.y += p.y; v.z += p.z; v.w += p.w;
    }
    *(float4*)(out + i) = v;
}

// =====================================================================
// pairwise interaction from U/V (UV layout [208][2048], V at col 1024)
// =====================================================================
__global__ __launch_bounds__(256) void pair_kernel(
    const float* __restrict__ UV, const float* __restrict__ b_i1,
    const float* __restrict__ W_i2, const float* __restrict__ b_i2,
    float* __restrict__ out)
{
    int p = blockIdx.x;
    int b = p / NPAIR_B, q = p % NPAIR_B;
    int i = q / (MAXN - 1), jj = q % (MAXN - 1);
    int j = jj + (jj >= i ? 1 : 0);
    const float* U = UV + (size_t)(b * MAXN + i) * (2 * NFB);
    const float* V = UV + (size_t)(b * MAXN + j) * (2 * NFB) + NFB;

    int tid = threadIdx.x, lane = tid & 31, wid = tid >> 5;
    int c = tid * 4;
    __shared__ float sred[16];

    float4 u  = *(const float4*)(U + c);
    float4 v  = *(const float4*)(V + c);
    float4 bi = *(const float4*)(b_i1 + c);
    float4 w0 = *(const float4*)(W_i2 + c);
    float4 w1 = *(const float4*)(W_i2 + NFB + c);

    float t0 = fmaxf(u.x + v.x + bi.x, 0.f);
    float t1 = fmaxf(u.y + v.y + bi.y, 0.f);
    float t2 = fmaxf(u.z + v.z + bi.z, 0.f);
    float t3 = fmaxf(u.w + v.w + bi.w, 0.f);
    float a0 = t0 * w0.x + t1 * w0.y + t2 * w0.z + t3 * w0.w;
    float a1 = t0 * w1.x + t1 * w1.y + t2 * w1.z + t3 * w1.w;
#pragma unroll
    for (int s = 16; s; s >>= 1) {
        a0 += __shfl_down_sync(0xffffffffu, a0, s);
        a1 += __shfl_down_sync(0xffffffffu, a1, s);
    }
    if (lane == 0) { sred[wid * 2] = a0; sred[wid * 2 + 1] = a1; }
    __syncthreads();
    if (tid < 2) {
        float s = 0.f;
#pragma unroll
        for (int w = 0; w < 8; ++w) s += sred[w * 2 + tid];
        out[p * 2 + tid] = s + b_i2[tid];
    }
}

// =====================================================================
// launch
// =====================================================================
extern "C" void kernel_launch(void* const* d_in, const int* in_sizes, int n_in,
                              void* d_out, int out_size)
{
    const float* features = (const float*)d_in[0];
    const float* boxes    = (const float*)d_in[1];
    const float* W_emb = (const float*)d_in[3];
    const float* b_emb = (const float*)d_in[4];
    const float* ln_g  = (const float*)d_in[5];
    const float* ln_b  = (const float*)d_in[6];
    const float* W_act = (const float*)d_in[7];
    const float* b_act = (const float*)d_in[8];
    const float* W_i1  = (const float*)d_in[9];
    const float* b_i1  = (const float*)d_in[10];
    const float* W_i2  = (const float*)d_in[11];
    const float* b_i2  = (const float*)d_in[12];
    float* out = (float*)d_out;

    void *aeh, *ael, *be, *bu, *fh, *fl, *pp, *uvpp, *uvp;
    cudaGetSymbolAddress(&aeh, g_Ae_h); cudaGetSymbolAddress(&ael, g_Ae_l);
    cudaGetSymbolAddress(&be, g_Be);    cudaGetSymbolAddress(&bu, g_Bu);
    cudaGetSymbolAddress(&fh, g_f_h);   cudaGetSymbolAddress(&fl, g_f_l);
    cudaGetSymbolAddress(&pp, g_part);  cudaGetSymbolAddress(&uvpp, g_UVp);
    cudaGetSymbolAddress(&uvp, g_UV);

    static int smem_set = 0;
    if (!smem_set) {
        cudaFuncSetAttribute(hmma_gemm, cudaFuncAttributeMaxDynamicSharedMemorySize, SMEM_DYN);
        smem_set = 1;
    }

    // operand prep
    conv_wemb<<<dim3(KPAD_E / 2048, NFB), 256>>>(W_emb, (__half*)be);
    conv_wi1 <<<2 * NFB, 128>>>(W_i1, (__half*)bu);
    roi_align_kernel<<<dim3(D_CH / 32, R_TOT), 256>>>(features, boxes,
                                                      (__half*)aeh, (__half*)ael);

    // embedding GEMM: [208 x 26624] x [1024 x 26624]^T, split-K=32, N tile 256
    hmma_gemm<<<dim3(NFB / 256, 4, KSPLIT), 256, SMEM_DYN>>>(
        (const __half*)aeh, (const __half*)ael, (const __half*)be,
        KPAD_E, KT_E, (float*)pp, (long)R_TOT * NFB, NFB, R_TOT);

    // reduce + LN + ReLU + action head
    ln_act_kernel<<<R_TOT, 256>>>((const float*)pp, b_emb, ln_g, ln_b, W_act, b_act,
                                  (__half*)fh, (__half*)fl, out);

    // UV GEMM: [208 x 1024] x [2048 x 1024]^T, split-K=4 -> partials
    hmma_gemm<<<dim3(2 * NFB / 256, 4, KSPLIT_U), 256, SMEM_DYN>>>(
        (const __half*)fh, (const __half*)fl, (const __half*)bu,
        KPAD_U, KT_U, (float*)uvpp, (long)R_TOT * 2 * NFB, 2 * NFB, R_TOT);
    uv_reduce<<<(R_TOT * 2 * NFB) / (256 * 4), 256>>>((const float*)uvpp, (float*)uvp);

    // pairwise combine + interaction head
    pair_kernel<<<NPAIR, 256>>>((const float*)uvp, b_i1, W_i2, b_i2, out + R_TOT * NA);
}

// round 7
// speedup vs baseline: 4.9647x; 1.0341x over previous
#include <cuda_runtime.h>
#include <cuda_fp16.h>
#include <cstdint>

// ---------------- problem constants ----------------
#define BT    16
#define D_CH  1056
#define OH    57
#define OW    87
#define MAXN  13
#define KK    5
#define NFB   1024
#define NA    6
#define R_TOT 208
#define KDIM  26400
#define KPAD_E 26624              // 832 * 32
#define KSPLIT 32
#define KT_E   (KPAD_E/32/KSPLIT) // 26 k-chunks (of 32) per split
#define KPAD_U 1024
#define KSPLIT_U 4
#define KT_U   (KPAD_U/32/KSPLIT_U) // 8
#define NPAIR_B 156
#define NPAIR   2496
#define MROWS 256

// ---------------- scratch (device globals; zero-initialized) ----------------
__device__ __align__(16) __half g_Ae_h[MROWS * KPAD_E];
__device__ __align__(16) __half g_Ae_l[MROWS * KPAD_E];
__device__ __align__(16) __half g_Be  [NFB * KPAD_E];
__device__ __align__(16) __half g_Bu  [2 * NFB * KPAD_U];
__device__ __align__(16) __half g_f_h [MROWS * NFB];
__device__ __align__(16) __half g_f_l [MROWS * NFB];
__device__ float g_part[KSPLIT * R_TOT * NFB];
__device__ float g_UVp [KSPLIT_U * R_TOT * 2 * NFB];
__device__ float g_UV  [R_TOT * 2 * NFB];

// ---------------- helpers ----------------
__device__ __forceinline__ uint32_t smem_u32(const void* p) {
    uint32_t a;
    asm("{ .reg .u64 t; cvta.to.shared.u64 t, %1; cvt.u32.u64 %0, t; }"
        : "=r"(a) : "l"(p));
    return a;
}
__device__ __forceinline__ void cp16(uint32_t dst, const void* src) {
    asm volatile("cp.async.cg.shared.global [%0], [%1], 16;" :: "r"(dst), "l"(src));
}
#define CP_COMMIT() asm volatile("cp.async.commit_group;" ::: "memory")

#define LDM4(R, addr) \
    asm volatile("ldmatrix.sync.aligned.m8n8.x4.shared.b16 {%0,%1,%2,%3}, [%4];" \
        : "=r"((R)[0]), "=r"((R)[1]), "=r"((R)[2]), "=r"((R)[3]) : "r"(addr))

#define MMA(D, A, B0, B1) \
    asm volatile("mma.sync.aligned.m16n8k16.row.col.f32.f16.f16.f32 " \
        "{%0,%1,%2,%3}, {%4,%5,%6,%7}, {%8,%9}, {%0,%1,%2,%3};" \
        : "+f"((D)[0]), "+f"((D)[1]), "+f"((D)[2]), "+f"((D)[3]) \
        : "r"((A)[0]), "r"((A)[1]), "r"((A)[2]), "r"((A)[3]), "r"(B0), "r"(B1))

__device__ __forceinline__ void split_h(float x, __half& h, __half& l) {
    h = __float2half_rn(x);
    l = __float2half_rn(x - __half2float(h));
}

// =====================================================================
// converters (vectorized: 8 elems/thread, 16B stores)
// =====================================================================
__global__ __launch_bounds__(256) void conv_wemb(
    const float* __restrict__ W, __half* __restrict__ o)
{
    int f = blockIdx.y;
    int k0 = (blockIdx.x * 256 + threadIdx.x) * 8;
    __half h[8];
    const float* src = W + (size_t)f * KDIM + k0;
    if (k0 + 8 <= KDIM) {
        float4 v0 = *(const float4*)src;
        float4 v1 = *(const float4*)(src + 4);
        h[0] = __float2half_rn(v0.x); h[1] = __float2half_rn(v0.y);
        h[2] = __float2half_rn(v0.z); h[3] = __float2half_rn(v0.w);
        h[4] = __float2half_rn(v1.x); h[5] = __float2half_rn(v1.y);
        h[6] = __float2half_rn(v1.z); h[7] = __float2half_rn(v1.w);
    } else {
#pragma unroll
        for (int i = 0; i < 8; ++i)
            h[i] = (k0 + i < KDIM) ? __float2half_rn(src[i]) : __ushort_as_half(0);
    }
    *(uint4*)(o + (size_t)f * KPAD_E + k0) = *(const uint4*)h;
}

__global__ __launch_bounds__(128) void conv_wi1(
    const float* __restrict__ W, __half* __restrict__ o)
{
    int f = blockIdx.x;
    int k0 = threadIdx.x * 8;
    const float* src = (f < NFB) ? W + (size_t)f * (2 * NFB) + k0
                                 : W + (size_t)(f - NFB) * (2 * NFB) + NFB + k0;
    float4 v0 = *(const float4*)src;
    float4 v1 = *(const float4*)(src + 4);
    __half h[8];
    h[0] = __float2half_rn(v0.x); h[1] = __float2half_rn(v0.y);
    h[2] = __float2half_rn(v0.z); h[3] = __float2half_rn(v0.w);
    h[4] = __float2half_rn(v1.x); h[5] = __float2half_rn(v1.y);
    h[6] = __float2half_rn(v1.z); h[7] = __float2half_rn(v1.w);
    *(uint4*)(o + (size_t)f * KPAD_U + k0) = *(const uint4*)h;
}

// =====================================================================
// ROI align -> fp16 hi/lo A operand (+ pad-zero fold on blockIdx.x==0)
// =====================================================================
__global__ __launch_bounds__(256) void roi_align_kernel(
    const float* __restrict__ feat, const float* __restrict__ boxes,
    __half* __restrict__ ah, __half* __restrict__ al)
{
    int r  = blockIdx.y;
    int d0 = blockIdx.x * 32;
    int b  = r / MAXN;
    const float* bx = boxes + r * 4;
    float x1 = bx[0], y1 = bx[1], x2 = bx[2], y2 = bx[3];
    float bw = (x2 - x1) * (1.0f / KK);
    float bh = (y2 - y1) * (1.0f / KK);

    int tid = threadIdx.x;
    int dl = tid >> 3, pl = tid & 7;
    const float* fb = feat + (size_t)(b * D_CH + d0 + dl) * (OH * OW);

    __shared__ float tile[32][25];
    for (int p = pl; p < 25; p += 8) {
        int iy = p / 5, jx = p % 5;
        float xs = x1 + (jx + 0.5f) * bw;
        float ys = y1 + (iy + 0.5f) * bh;
        float x0f = floorf(xs), y0f = floorf(ys);
        float lx = xs - x0f, ly = ys - y0f;
        int x0 = (int)x0f, y0 = (int)y0f;
        int x0i = min(max(x0, 0), OW - 1);
        int x1i = min(max(x0 + 1, 0), OW - 1);
        int y0i = min(max(y0, 0), OH - 1);
        int y1i = min(max(y0 + 1, 0), OH - 1);
        float v00 = fb[y0i * OW + x0i], v01 = fb[y0i * OW + x1i];
        float v10 = fb[y1i * OW + x0i], v11 = fb[y1i * OW + x1i];
        float wy0 = 1.f - ly, wx0 = 1.f - lx;
        tile[dl][p] = v00 * wy0 * wx0 + v01 * wy0 * lx
                    + v10 * ly  * wx0 + v11 * ly  * lx;
    }
    __syncthreads();
    size_t base = (size_t)r * KPAD_E + d0 * 25;  // 800-aligned offset, even
    const float* src = &tile[0][0];
    for (int t = tid; t < 400; t += 256) {
        float s0 = src[2 * t], s1 = src[2 * t + 1];
        __half h0, l0, h1, l1;
        split_h(s0, h0, l0); split_h(s1, h1, l1);
        *(__half2*)(ah + base + 2 * t) = __halves2half2(h0, h1);
        *(__half2*)(al + base + 2 * t) = __halves2half2(l0, l1);
    }
    // fold pad-zero: cols [KDIM, KPAD_E) of row r (224 halves = 28 uint4)
    if (blockIdx.x == 0 && tid < 28) {
        uint4 z = make_uint4(0, 0, 0, 0);
        *(uint4*)(ah + (size_t)r * KPAD_E + KDIM + tid * 8) = z;
        *(uint4*)(al + (size_t)r * KPAD_E + KDIM + tid * 8) = z;
    }
}

// =====================================================================
// HMMA fp16 split-2 GEMM: C[z] = (Ah + Al) * B^T   (B pre-rounded fp16)
//   block tile 64(M) x 256(N) x 32(K), 8 warps (2M x 4N, warp tile 32x64),
//   3-stage cp.async pipeline, row stride 80B, dead-M-row skip,
//   hazard-free MMA order: all-hi pass then all-lo pass (reuse distance 16)
// =====================================================================
#define ROWB 80
#define AH_OFF 0
#define AL_OFF (64 * ROWB)              // 5120
#define B_OFF  (2 * 64 * ROWB)          // 10240
#define STAGE_SZ (B_OFF + 256 * ROWB)   // 30720
#define NSTAGE 3
#define SMEM_DYN (NSTAGE * STAGE_SZ)    // 92160

__global__ __launch_bounds__(256, 2) void hmma_gemm(
    const __half* __restrict__ Ah, const __half* __restrict__ Al,
    const __half* __restrict__ B,
    int kPad, int kTiles, float* __restrict__ C, long cZstride,
    int Nld, int Mreal)
{
    extern __shared__ char smraw[];
    const uint32_t sm = smem_u32(smraw);
    const int tid = threadIdx.x;
    const int lane = tid & 31, wid = tid >> 5;
    const int wm = wid & 1, wn = wid >> 1;          // 2 M-warps x 4 N-warps
    const int n0 = blockIdx.x * 256, m0 = blockIdx.y * 64, z = blockIdx.z;
    const long k00 = (long)z * kTiles * 32;
    C += (long)z * cZstride;

    // per-warp activity (M blocks of 16; Mreal is a multiple of 16)
    const bool act0 = (m0 + wm * 32)      < Mreal;
    const bool act1 = (m0 + wm * 32 + 16) < Mreal;

    // ---- load maps: A 128 rows (64 hi + 64 lo) = 2 cp16/thr, B 256 rows = 4 cp16/thr
    const int lrow = tid >> 2, lc = tid & 3;        // lrow 0..63, lc 0..3
    const __half* aHp = Ah + (size_t)(m0 + lrow) * kPad + lc * 8;
    const __half* aLp = Al + (size_t)(m0 + lrow) * kPad + lc * 8;
    const __half* bP[4];
#pragma unroll
    for (int p = 0; p < 4; ++p)
        bP[p] = B + (size_t)(n0 + p * 64 + lrow) * kPad + lc * 8;
    const uint32_t aDst = lrow * ROWB + lc * 16;
    const uint32_t bDstBase = lrow * ROWB + lc * 16;

    // ---- ldmatrix per-lane bases
    const uint32_t aLdm = sm + (wm * 32 + (lane & 15)) * ROWB + (lane >> 4) * 16;
    const uint32_t bLdm = sm + B_OFF + (wn * 64 + (lane & 15)) * ROWB + (lane >> 4) * 16;

    float d[2][8][4];
#pragma unroll
    for (int mi = 0; mi < 2; ++mi)
#pragma unroll
        for (int ni = 0; ni < 8; ++ni)
#pragma unroll
            for (int q = 0; q < 4; ++q) d[mi][ni][q] = 0.f;

    auto load_stage = [&](int s, int kt) {
        long ke = k00 + (long)kt * 32;
        uint32_t st = sm + s * STAGE_SZ;
        cp16(st + AH_OFF + aDst, aHp + ke);
        cp16(st + AL_OFF + aDst, aLp + ke);
#pragma unroll
        for (int p = 0; p < 4; ++p)
            cp16(st + B_OFF + bDstBase + p * (64 * ROWB), bP[p] + ke);
        CP_COMMIT();
    };

    // prologue: fill 2 of 3 stages
    load_stage(0, 0);
    load_stage(1, 1);

    int s = 0;
    for (int kt = 0; kt < kTiles; ++kt) {
        if (kt + 2 < kTiles) {
            int s2 = s + 2; if (s2 >= NSTAGE) s2 -= NSTAGE;
            load_stage(s2, kt + 2);
            asm volatile("cp.async.wait_group 2;" ::: "memory");
        } else if (kt + 1 < kTiles) {
            asm volatile("cp.async.wait_group 1;" ::: "memory");
        } else {
            asm volatile("cp.async.wait_group 0;" ::: "memory");
        }
        __syncthreads();

        uint32_t stA = aLdm + s * STAGE_SZ;
        uint32_t stB = bLdm + s * STAGE_SZ;
#pragma unroll
        for (int ks = 0; ks < 2; ++ks) {
            uint32_t ah[2][4], al_[2][4], b[4][4];
#pragma unroll
            for (int pr = 0; pr < 4; ++pr)
                LDM4(b[pr], stB + pr * (16 * ROWB) + ks * 32);
            if (act0) {
                LDM4(ah[0],  stA + AH_OFF + ks * 32);
                LDM4(al_[0], stA + AL_OFF + ks * 32);
            }
            if (act1) {
                LDM4(ah[1],  stA + AH_OFF + 16 * ROWB + ks * 32);
                LDM4(al_[1], stA + AL_OFF + 16 * ROWB + ks * 32);
            }
            // ---- pass 1: all hi-MMAs (16 independent accumulators)
#pragma unroll
            for (int mi = 0; mi < 2; ++mi) {
                if (mi == 0 ? !act0 : !act1) continue;
#pragma unroll
                for (int ni = 0; ni < 8; ++ni) {
                    int pr = ni >> 1, hi = ni & 1;
                    MMA(d[mi][ni], ah[mi], b[pr][hi], b[pr][hi + 2]);
                }
            }
            // ---- pass 2: all lo-MMAs (reuse distance 16 from pass 1)
#pragma unroll
            for (int mi = 0; mi < 2; ++mi) {
                if (mi == 0 ? !act0 : !act1) continue;
#pragma unroll
                for (int ni = 0; ni < 8; ++ni) {
                    int pr = ni >> 1, hi = ni & 1;
                    MMA(d[mi][ni], al_[mi], b[pr][hi], b[pr][hi + 2]);
                }
            }
        }
        __syncthreads();
        if (++s == NSTAGE) s = 0;
    }

    // ---- epilogue
#pragma unroll
    for (int mi = 0; mi < 2; ++mi) {
        int r0 = m0 + wm * 32 + mi * 16 + (lane >> 2);
        int r1 = r0 + 8;
#pragma unroll
        for (int ni = 0; ni < 8; ++ni) {
            int col = n0 + wn * 64 + ni * 8 + (lane & 3) * 2;
            if (r0 < Mreal)
                *(float2*)(C + (size_t)r0 * Nld + col) = make_float2(d[mi][ni][0], d[mi][ni][1]);
            if (r1 < Mreal)
                *(float2*)(C + (size_t)r1 * Nld + col) = make_float2(d[mi][ni][2], d[mi][ni][3]);
        }
    }
}

// =====================================================================
// split-K reduce + bias + LayerNorm + ReLU + action head; emits fp16 hi/lo
// =====================================================================
__global__ __launch_bounds__(256) void ln_act_kernel(
    const float* __restrict__ partial, const float* __restrict__ b_emb,
    const float* __restrict__ ln_g, const float* __restrict__ ln_b,
    const float* __restrict__ W_act, const float* __restrict__ b_act,
    __half* __restrict__ fH, __half* __restrict__ fL,
    float* __restrict__ out_act)
{
    int m = blockIdx.x, tid = threadIdx.x;
    int c = tid * 4;
    int lane = tid & 31, wid = tid >> 5;
    __shared__ float sred[48];

    float4 v = *(const float4*)(b_emb + c);
#pragma unroll
    for (int s = 0; s < KSPLIT; ++s) {
        float4 p = *(const float4*)(partial + ((size_t)s * R_TOT + m) * NFB + c);
        v.x += p.x; v.y += p.y; v.z += p.z; v.w += p.w;
    }
    float S = v.x + v.y + v.z + v.w;
    float SS = v.x * v.x + v.y * v.y + v.z * v.z + v.w * v.w;
#pragma unroll
    for (int o = 16; o; o >>= 1) {
        S  += __shfl_down_sync(0xffffffffu, S,  o);
        SS += __shfl_down_sync(0xffffffffu, SS, o);
    }
    if (lane == 0) { sred[wid * 2] = S; sred[wid * 2 + 1] = SS; }
    __syncthreads();
    float tS = 0.f, tSS = 0.f;
#pragma unroll
    for (int w = 0; w < 8; ++w) { tS += sred[w * 2]; tSS += sred[w * 2 + 1]; }
    float mean = tS * (1.0f / NFB);
    float var  = tSS * (1.0f / NFB) - mean * mean;
    float rstd = rsqrtf(var + 1e-5f);

    float4 g = *(const float4*)(ln_g + c);
    float4 bb = *(const float4*)(ln_b + c);
    float f0 = fmaxf((v.x - mean) * rstd * g.x + bb.x, 0.f);
    float f1 = fmaxf((v.y - mean) * rstd * g.y + bb.y, 0.f);
    float f2 = fmaxf((v.z - mean) * rstd * g.z + bb.z, 0.f);
    float f3 = fmaxf((v.w - mean) * rstd * g.w + bb.w, 0.f);

    size_t fo = (size_t)m * NFB + c;
    __half h, l;
    split_h(f0, h, l); fH[fo + 0] = h; fL[fo + 0] = l;
    split_h(f1, h, l); fH[fo + 1] = h; fL[fo + 1] = l;
    split_h(f2, h, l); fH[fo + 2] = h; fL[fo + 2] = l;
    split_h(f3, h, l); fH[fo + 3] = h; fL[fo + 3] = l;

    float a[NA];
#pragma unroll
    for (int o = 0; o < NA; ++o) {
        float4 w = *(const float4*)(W_act + (size_t)o * NFB + c);
        a[o] = f0 * w.x + f1 * w.y + f2 * w.z + f3 * w.w;
    }
    __syncthreads();
#pragma unroll
    for (int o = 0; o < NA; ++o) {
#pragma unroll
        for (int s = 16; s; s >>= 1) a[o] += __shfl_down_sync(0xffffffffu, a[o], s);
        if (lane == 0) sred[wid * NA + o] = a[o];
    }
    __syncthreads();
    if (tid < NA) {
        float s = 0.f;
#pragma unroll
        for (int w = 0; w < 8; ++w) s += sred[w * NA + tid];
        out_act[m * NA + tid] = s + b_act[tid];
    }
}

// =====================================================================
// UV split-K reduce
// =====================================================================
__global__ __launch_bounds__(256) void uv_reduce(
    const float* __restrict__ part, float* __restrict__ out)
{
    size_t i = ((size_t)blockIdx.x * 256 + threadIdx.x) * 4;
    float4 v = *(const float4*)(part + i);
#pragma unroll
    for (int s = 1; s < KSPLIT_U; ++s) {
        float4 p = *(const float4*)(part + (size_t)s * R_TOT * 2 * NFB + i);
        v.x += p.x; v.y += p.y; v.z += p.z; v.w += p.w;
    }
    *(float4*)(out + i) = v;
}

// =====================================================================
// pairwise interaction from U/V (UV layout [208][2048], V at col 1024)
// =====================================================================
__global__ __launch_bounds__(256) void pair_kernel(
    const float* __restrict__ UV, const float* __restrict__ b_i1,
    const float* __restrict__ W_i2, const float* __restrict__ b_i2,
    float* __restrict__ out)
{
    int p = blockIdx.x;
    int b = p / NPAIR_B, q = p % NPAIR_B;
    int i = q / (MAXN - 1), jj = q % (MAXN - 1);
    int j = jj + (jj >= i ? 1 : 0);
    const float* U = UV + (size_t)(b * MAXN + i) * (2 * NFB);
    const float* V = UV + (size_t)(b * MAXN + j) * (2 * NFB) + NFB;

    int tid = threadIdx.x, lane = tid & 31, wid = tid >> 5;
    int c = tid * 4;
    __shared__ float sred[16];

    float4 u  = *(const float4*)(U + c);
    float4 v  = *(const float4*)(V + c);
    float4 bi = *(const float4*)(b_i1 + c);
    float4 w0 = *(const float4*)(W_i2 + c);
    float4 w1 = *(const float4*)(W_i2 + NFB + c);

    float t0 = fmaxf(u.x + v.x + bi.x, 0.f);
    float t1 = fmaxf(u.y + v.y + bi.y, 0.f);
    float t2 = fmaxf(u.z + v.z + bi.z, 0.f);
    float t3 = fmaxf(u.w + v.w + bi.w, 0.f);
    float a0 = t0 * w0.x + t1 * w0.y + t2 * w0.z + t3 * w0.w;
    float a1 = t0 * w1.x + t1 * w1.y + t2 * w1.z + t3 * w1.w;
#pragma unroll
    for (int s = 16; s; s >>= 1) {
        a0 += __shfl_down_sync(0xffffffffu, a0, s);
        a1 += __shfl_down_sync(0xffffffffu, a1, s);
    }
    if (lane == 0) { sred[wid * 2] = a0; sred[wid * 2 + 1] = a1; }
    __syncthreads();
    if (tid < 2) {
        float s = 0.f;
#pragma unroll
        for (int w = 0; w < 8; ++w) s += sred[w * 2 + tid];
        out[p * 2 + tid] = s + b_i2[tid];
    }
}

// =====================================================================
// launch (multi-stream fork/join, graph-capturable)
// =====================================================================
extern "C" void kernel_launch(void* const* d_in, const int* in_sizes, int n_in,
                              void* d_out, int out_size)
{
    const float* features = (const float*)d_in[0];
    const float* boxes    = (const float*)d_in[1];
    const float* W_emb = (const float*)d_in[3];
    const float* b_emb = (const float*)d_in[4];
    const float* ln_g  = (const float*)d_in[5];
    const float* ln_b  = (const float*)d_in[6];
    const float* W_act = (const float*)d_in[7];
    const float* b_act = (const float*)d_in[8];
    const float* W_i1  = (const float*)d_in[9];
    const float* b_i1  = (const float*)d_in[10];
    const float* W_i2  = (const float*)d_in[11];
    const float* b_i2  = (const float*)d_in[12];
    float* out = (float*)d_out;

    void *aeh, *ael, *be, *bu, *fh, *fl, *pp, *uvpp, *uvp;
    cudaGetSymbolAddress(&aeh, g_Ae_h); cudaGetSymbolAddress(&ael, g_Ae_l);
    cudaGetSymbolAddress(&be, g_Be);    cudaGetSymbolAddress(&bu, g_Bu);
    cudaGetSymbolAddress(&fh, g_f_h);   cudaGetSymbolAddress(&fl, g_f_l);
    cudaGetSymbolAddress(&pp, g_part);  cudaGetSymbolAddress(&uvpp, g_UVp);
    cudaGetSymbolAddress(&uvp, g_UV);

    static cudaStream_t s1 = nullptr, s2 = nullptr;
    static cudaEvent_t evFork = nullptr, evWemb = nullptr, evWi1 = nullptr;
    if (!s1) {   // idempotent one-time setup on the (uncaptured) correctness call
        cudaFuncSetAttribute(hmma_gemm, cudaFuncAttributeMaxDynamicSharedMemorySize, SMEM_DYN);
        cudaStreamCreateWithFlags(&s1, cudaStreamNonBlocking);
        cudaStreamCreateWithFlags(&s2, cudaStreamNonBlocking);
        cudaEventCreateWithFlags(&evFork, cudaEventDisableTiming);
        cudaEventCreateWithFlags(&evWemb, cudaEventDisableTiming);
        cudaEventCreateWithFlags(&evWi1,  cudaEventDisableTiming);
    }

    // ---- fork: weight conversions on side streams, roi-align on main
    cudaEventRecord(evFork, 0);
    cudaStreamWaitEvent(s1, evFork, 0);
    cudaStreamWaitEvent(s2, evFork, 0);

    conv_wemb<<<dim3(KPAD_E / 2048, NFB), 256, 0, s1>>>(W_emb, (__half*)be);
    cudaEventRecord(evWemb, s1);
    conv_wi1<<<2 * NFB, 128, 0, s2>>>(W_i1, (__half*)bu);
    cudaEventRecord(evWi1, s2);

    roi_align_kernel<<<dim3(D_CH / 32, R_TOT), 256>>>(features, boxes,
                                                      (__half*)aeh, (__half*)ael);

    // ---- join W_emb before embedding GEMM
    cudaStreamWaitEvent(0, evWemb, 0);

    // embedding GEMM: [208 x 26624] x [1024 x 26624]^T, split-K=32, N tile 256
    hmma_gemm<<<dim3(NFB / 256, 4, KSPLIT), 256, SMEM_DYN>>>(
        (const __half*)aeh, (const __half*)ael, (const __half*)be,
        KPAD_E, KT_E, (float*)pp, (long)R_TOT * NFB, NFB, R_TOT);

    // reduce + LN + ReLU + action head
    ln_act_kernel<<<R_TOT, 256>>>((const float*)pp, b_emb, ln_g, ln_b, W_act, b_act,
                                  (__half*)fh, (__half*)fl, out);

    // ---- join W_i1 before UV GEMM
    cudaStreamWaitEvent(0, evWi1, 0);

    // UV GEMM: [208 x 1024] x [2048 x 1024]^T, split-K=4 -> partials
    hmma_gemm<<<dim3(2 * NFB / 256, 4, KSPLIT_U), 256, SMEM_DYN>>>(
        (const __half*)fh, (const __half*)fl, (const __half*)bu,
        KPAD_U, KT_U, (float*)uvpp, (long)R_TOT * 2 * NFB, 2 * NFB, R_TOT);
    uv_reduce<<<(R_TOT * 2 * NFB) / (256 * 4), 256>>>((const float*)uvpp, (float*)uvp);

    // pairwise combine + interaction head
    pair_kernel<<<NPAIR, 256>>>((const float*)uvp, b_i1, W_i2, b_i2, out + R_TOT * NA);
}

// round 8
// speedup vs baseline: 6.0881x; 1.2263x over previous
#include <cuda_runtime.h>
#include <cuda_fp16.h>
#include <cstdint>

// ---------------- problem constants ----------------
#define BT    16
#define D_CH  1056
#define OH    57
#define OW    87
#define MAXN  13
#define KK    5
#define NFB   1024
#define NA    6
#define R_TOT 208
#define KDIM  26400
#define KPAD_E 26624              // 832 * 32
#define KSPLIT 32
#define KT_E   (KPAD_E/32/KSPLIT) // 26 k-chunks (of 32) per split
#define KPAD_U 1024
#define KSPLIT_U 4
#define KT_U   (KPAD_U/32/KSPLIT_U) // 8
#define NPAIR_B 156
#define NPAIR   2496
#define MROWS 256

// ---------------- scratch (device globals; zero-initialized) ----------------
__device__ __align__(16) __half g_Ae [MROWS * KPAD_E];
__device__ __align__(16) __half g_Be [NFB * KPAD_E];
__device__ __align__(16) __half g_Bu [2 * NFB * KPAD_U];
__device__ __align__(16) __half g_f  [MROWS * NFB];
__device__ float g_part[KSPLIT * R_TOT * NFB];
__device__ float g_UVp [KSPLIT_U * R_TOT * 2 * NFB];
__device__ float g_UV  [R_TOT * 2 * NFB];

// ---------------- helpers ----------------
__device__ __forceinline__ uint32_t smem_u32(const void* p) {
    uint32_t a;
    asm("{ .reg .u64 t; cvta.to.shared.u64 t, %1; cvt.u32.u64 %0, t; }"
        : "=r"(a) : "l"(p));
    return a;
}
__device__ __forceinline__ void cp16(uint32_t dst, const void* src) {
    asm volatile("cp.async.cg.shared.global [%0], [%1], 16;" :: "r"(dst), "l"(src));
}
#define CP_COMMIT() asm volatile("cp.async.commit_group;" ::: "memory")

#define LDM4(R, addr) \
    asm volatile("ldmatrix.sync.aligned.m8n8.x4.shared.b16 {%0,%1,%2,%3}, [%4];" \
        : "=r"((R)[0]), "=r"((R)[1]), "=r"((R)[2]), "=r"((R)[3]) : "r"(addr))

#define MMA(D, A, B0, B1) \
    asm volatile("mma.sync.aligned.m16n8k16.row.col.f32.f16.f16.f32 " \
        "{%0,%1,%2,%3}, {%4,%5,%6,%7}, {%8,%9}, {%0,%1,%2,%3};" \
        : "+f"((D)[0]), "+f"((D)[1]), "+f"((D)[2]), "+f"((D)[3]) \
        : "r"((A)[0]), "r"((A)[1]), "r"((A)[2]), "r"((A)[3]), "r"(B0), "r"(B1))

// =====================================================================
// converters (vectorized: 8 elems/thread, 16B stores)
// =====================================================================
__global__ __launch_bounds__(256) void conv_wemb(
    const float* __restrict__ W, __half* __restrict__ o)
{
    int f = blockIdx.y;
    int k0 = (blockIdx.x * 256 + threadIdx.x) * 8;
    __half h[8];
    const float* src = W + (size_t)f * KDIM + k0;
    if (k0 + 8 <= KDIM) {
        float4 v0 = *(const float4*)src;
        float4 v1 = *(const float4*)(src + 4);
        h[0] = __float2half_rn(v0.x); h[1] = __float2half_rn(v0.y);
        h[2] = __float2half_rn(v0.z); h[3] = __float2half_rn(v0.w);
        h[4] = __float2half_rn(v1.x); h[5] = __float2half_rn(v1.y);
        h[6] = __float2half_rn(v1.z); h[7] = __float2half_rn(v1.w);
    } else {
#pragma unroll
        for (int i = 0; i < 8; ++i)
            h[i] = (k0 + i < KDIM) ? __float2half_rn(src[i]) : __ushort_as_half(0);
    }
    *(uint4*)(o + (size_t)f * KPAD_E + k0) = *(const uint4*)h;
}

__global__ __launch_bounds__(128) void conv_wi1(
    const float* __restrict__ W, __half* __restrict__ o)
{
    int f = blockIdx.x;
    int k0 = threadIdx.x * 8;
    const float* src = (f < NFB) ? W + (size_t)f * (2 * NFB) + k0
                                 : W + (size_t)(f - NFB) * (2 * NFB) + NFB + k0;
    float4 v0 = *(const float4*)src;
    float4 v1 = *(const float4*)(src + 4);
    __half h[8];
    h[0] = __float2half_rn(v0.x); h[1] = __float2half_rn(v0.y);
    h[2] = __float2half_rn(v0.z); h[3] = __float2half_rn(v0.w);
    h[4] = __float2half_rn(v1.x); h[5] = __float2half_rn(v1.y);
    h[6] = __float2half_rn(v1.z); h[7] = __float2half_rn(v1.w);
    *(uint4*)(o + (size_t)f * KPAD_U + k0) = *(const uint4*)h;
}

// =====================================================================
// ROI align -> fp16 A operand (+ pad-zero fold on blockIdx.x==0)
// =====================================================================
__global__ __launch_bounds__(256) void roi_align_kernel(
    const float* __restrict__ feat, const float* __restrict__ boxes,
    __half* __restrict__ ah)
{
    int r  = blockIdx.y;
    int d0 = blockIdx.x * 32;
    int b  = r / MAXN;
    const float* bx = boxes + r * 4;
    float x1 = bx[0], y1 = bx[1], x2 = bx[2], y2 = bx[3];
    float bw = (x2 - x1) * (1.0f / KK);
    float bh = (y2 - y1) * (1.0f / KK);

    int tid = threadIdx.x;
    int dl = tid >> 3, pl = tid & 7;
    const float* fb = feat + (size_t)(b * D_CH + d0 + dl) * (OH * OW);

    __shared__ float tile[32][25];
    for (int p = pl; p < 25; p += 8) {
        int iy = p / 5, jx = p % 5;
        float xs = x1 + (jx + 0.5f) * bw;
        float ys = y1 + (iy + 0.5f) * bh;
        float x0f = floorf(xs), y0f = floorf(ys);
        float lx = xs - x0f, ly = ys - y0f;
        int x0 = (int)x0f, y0 = (int)y0f;
        int x0i = min(max(x0, 0), OW - 1);
        int x1i = min(max(x0 + 1, 0), OW - 1);
        int y0i = min(max(y0, 0), OH - 1);
        int y1i = min(max(y0 + 1, 0), OH - 1);
        float v00 = fb[y0i * OW + x0i], v01 = fb[y0i * OW + x1i];
        float v10 = fb[y1i * OW + x0i], v11 = fb[y1i * OW + x1i];
        float wy0 = 1.f - ly, wx0 = 1.f - lx;
        tile[dl][p] = v00 * wy0 * wx0 + v01 * wy0 * lx
                    + v10 * ly  * wx0 + v11 * ly  * lx;
    }
    __syncthreads();
    size_t base = (size_t)r * KPAD_E + d0 * 25;  // even offset
    const float* src = &tile[0][0];
    for (int t = tid; t < 400; t += 256) {
        *(__half2*)(ah + base + 2 * t) =
            __halves2half2(__float2half_rn(src[2 * t]), __float2half_rn(src[2 * t + 1]));
    }
    // fold pad-zero: cols [KDIM, KPAD_E) of row r (224 halves = 28 uint4)
    if (blockIdx.x == 0 && tid < 28) {
        uint4 z = make_uint4(0, 0, 0, 0);
        *(uint4*)(ah + (size_t)r * KPAD_E + KDIM + tid * 8) = z;
    }
}

// =====================================================================
// HMMA fp16 GEMM: C[z] = A * B^T  (A, B pre-rounded fp16)
//   block tile 64(M) x 256(N) x 32(K), 8 warps (2M x 4N, warp tile 32x64),
//   3-stage cp.async pipeline, row stride 80B, dead-M-row skip
// =====================================================================
#define ROWB 80
#define A_OFF 0
#define B_OFF  (64 * ROWB)              // 5120
#define STAGE_SZ (B_OFF + 256 * ROWB)   // 25600
#define NSTAGE 3
#define SMEM_DYN (NSTAGE * STAGE_SZ)    // 76800

__global__ __launch_bounds__(256, 2) void hmma_gemm(
    const __half* __restrict__ A, const __half* __restrict__ B,
    int kPad, int kTiles, float* __restrict__ C, long cZstride,
    int Nld, int Mreal)
{
    extern __shared__ char smraw[];
    const uint32_t sm = smem_u32(smraw);
    const int tid = threadIdx.x;
    const int lane = tid & 31, wid = tid >> 5;
    const int wm = wid & 1, wn = wid >> 1;          // 2 M-warps x 4 N-warps
    const int n0 = blockIdx.x * 256, m0 = blockIdx.y * 64, z = blockIdx.z;
    const long k00 = (long)z * kTiles * 32;
    C += (long)z * cZstride;

    // per-warp activity (M blocks of 16; Mreal is a multiple of 16)
    const bool act0 = (m0 + wm * 32)      < Mreal;
    const bool act1 = (m0 + wm * 32 + 16) < Mreal;

    // ---- load maps: A 64 rows = 1 cp16/thr, B 256 rows = 4 cp16/thr
    const int lrow = tid >> 2, lc = tid & 3;        // lrow 0..63, lc 0..3
    const __half* aP = A + (size_t)(m0 + lrow) * kPad + lc * 8;
    const __half* bP[4];
#pragma unroll
    for (int p = 0; p < 4; ++p)
        bP[p] = B + (size_t)(n0 + p * 64 + lrow) * kPad + lc * 8;
    const uint32_t aDst = lrow * ROWB + lc * 16;
    const uint32_t bDstBase = lrow * ROWB + lc * 16;

    // ---- ldmatrix per-lane bases
    const uint32_t aLdm = sm + (wm * 32 + (lane & 15)) * ROWB + (lane >> 4) * 16;
    const uint32_t bLdm = sm + B_OFF + (wn * 64 + (lane & 15)) * ROWB + (lane >> 4) * 16;

    float d[2][8][4];
#pragma unroll
    for (int mi = 0; mi < 2; ++mi)
#pragma unroll
        for (int ni = 0; ni < 8; ++ni)
#pragma unroll
            for (int q = 0; q < 4; ++q) d[mi][ni][q] = 0.f;

    auto load_stage = [&](int s, int kt) {
        long ke = k00 + (long)kt * 32;
        uint32_t st = sm + s * STAGE_SZ;
        cp16(st + A_OFF + aDst, aP + ke);
#pragma unroll
        for (int p = 0; p < 4; ++p)
            cp16(st + B_OFF + bDstBase + p * (64 * ROWB), bP[p] + ke);
        CP_COMMIT();
    };

    // prologue: fill 2 of 3 stages
    load_stage(0, 0);
    load_stage(1, 1);

    int s = 0;
    for (int kt = 0; kt < kTiles; ++kt) {
        if (kt + 2 < kTiles) {
            int s2 = s + 2; if (s2 >= NSTAGE) s2 -= NSTAGE;
            load_stage(s2, kt + 2);
            asm volatile("cp.async.wait_group 2;" ::: "memory");
        } else if (kt + 1 < kTiles) {
            asm volatile("cp.async.wait_group 1;" ::: "memory");
        } else {
            asm volatile("cp.async.wait_group 0;" ::: "memory");
        }
        __syncthreads();

        uint32_t stA = aLdm + s * STAGE_SZ;
        uint32_t stB = bLdm + s * STAGE_SZ;
#pragma unroll
        for (int ks = 0; ks < 2; ++ks) {
            uint32_t ah[2][4], b[4][4];
#pragma unroll
            for (int pr = 0; pr < 4; ++pr)
                LDM4(b[pr], stB + pr * (16 * ROWB) + ks * 32);
            if (act0) LDM4(ah[0], stA + A_OFF + ks * 32);
            if (act1) LDM4(ah[1], stA + A_OFF + 16 * ROWB + ks * 32);
#pragma unroll
            for (int mi = 0; mi < 2; ++mi) {
                if (mi == 0 ? !act0 : !act1) continue;
#pragma unroll
                for (int ni = 0; ni < 8; ++ni) {
                    int pr = ni >> 1, hi = ni & 1;
                    MMA(d[mi][ni], ah[mi], b[pr][hi], b[pr][hi + 2]);
                }
            }
        }
        __syncthreads();
        if (++s == NSTAGE) s = 0;
    }

    // ---- epilogue
#pragma unroll
    for (int mi = 0; mi < 2; ++mi) {
        int r0 = m0 + wm * 32 + mi * 16 + (lane >> 2);
        int r1 = r0 + 8;
#pragma unroll
        for (int ni = 0; ni < 8; ++ni) {
            int col = n0 + wn * 64 + ni * 8 + (lane & 3) * 2;
            if (r0 < Mreal)
                *(float2*)(C + (size_t)r0 * Nld + col) = make_float2(d[mi][ni][0], d[mi][ni][1]);
            if (r1 < Mreal)
                *(float2*)(C + (size_t)r1 * Nld + col) = make_float2(d[mi][ni][2], d[mi][ni][3]);
        }
    }
}

// =====================================================================
// split-K reduce + bias + LayerNorm + ReLU + action head; emits fp16
// =====================================================================
__global__ __launch_bounds__(256) void ln_act_kernel(
    const float* __restrict__ partial, const float* __restrict__ b_emb,
    const float* __restrict__ ln_g, const float* __restrict__ ln_b,
    const float* __restrict__ W_act, const float* __restrict__ b_act,
    __half* __restrict__ fH, float* __restrict__ out_act)
{
    int m = blockIdx.x, tid = threadIdx.x;
    int c = tid * 4;
    int lane = tid & 31, wid = tid >> 5;
    __shared__ float sred[48];

    float4 v = *(const float4*)(b_emb + c);
#pragma unroll
    for (int s = 0; s < KSPLIT; ++s) {
        float4 p = *(const float4*)(partial + ((size_t)s * R_TOT + m) * NFB + c);
        v.x += p.x; v.y += p.y; v.z += p.z; v.w += p.w;
    }
    float S = v.x + v.y + v.z + v.w;
    float SS = v.x * v.x + v.y * v.y + v.z * v.z + v.w * v.w;
#pragma unroll
    for (int o = 16; o; o >>= 1) {
        S  += __shfl_down_sync(0xffffffffu, S,  o);
        SS += __shfl_down_sync(0xffffffffu, SS, o);
    }
    if (lane == 0) { sred[wid * 2] = S; sred[wid * 2 + 1] = SS; }
    __syncthreads();
    float tS = 0.f, tSS = 0.f;
#pragma unroll
    for (int w = 0; w < 8; ++w) { tS += sred[w * 2]; tSS += sred[w * 2 + 1]; }
    float mean = tS * (1.0f / NFB);
    float var  = tSS * (1.0f / NFB) - mean * mean;
    float rstd = rsqrtf(var + 1e-5f);

    float4 g = *(const float4*)(ln_g + c);
    float4 bb = *(const float4*)(ln_b + c);
    float f0 = fmaxf((v.x - mean) * rstd * g.x + bb.x, 0.f);
    float f1 = fmaxf((v.y - mean) * rstd * g.y + bb.y, 0.f);
    float f2 = fmaxf((v.z - mean) * rstd * g.z + bb.z, 0.f);
    float f3 = fmaxf((v.w - mean) * rstd * g.w + bb.w, 0.f);

    size_t fo = (size_t)m * NFB + c;
    *(__half2*)(fH + fo)     = __halves2half2(__float2half_rn(f0), __float2half_rn(f1));
    *(__half2*)(fH + fo + 2) = __halves2half2(__float2half_rn(f2), __float2half_rn(f3));

    float a[NA];
#pragma unroll
    for (int o = 0; o < NA; ++o) {
        float4 w = *(const float4*)(W_act + (size_t)o * NFB + c);
        a[o] = f0 * w.x + f1 * w.y + f2 * w.z + f3 * w.w;
    }
    __syncthreads();
#pragma unroll
    for (int o = 0; o < NA; ++o) {
#pragma unroll
        for (int s = 16; s; s >>= 1) a[o] += __shfl_down_sync(0xffffffffu, a[o], s);
        if (lane == 0) sred[wid * NA + o] = a[o];
    }
    __syncthreads();
    if (tid < NA) {
        float s = 0.f;
#pragma unroll
        for (int w = 0; w < 8; ++w) s += sred[w * NA + tid];
        out_act[m * NA + tid] = s + b_act[tid];
    }
}

// =====================================================================
// UV split-K reduce
// =====================================================================
__global__ __launch_bounds__(256) void uv_reduce(
    const float* __restrict__ part, float* __restrict__ out)
{
    size_t i = ((size_t)blockIdx.x * 256 + threadIdx.x) * 4;
    float4 v = *(const float4*)(part + i);
#pragma unroll
    for (int s = 1; s < KSPLIT_U; ++s) {
        float4 p = *(const float4*)(part + (size_t)s * R_TOT * 2 * NFB + i);
        v.x += p.x; v.y += p.y; v.z += p.z; v.w += p.w;
    }
    *(float4*)(out + i) = v;
}

// =====================================================================
// pairwise interaction from U/V (UV layout [208][2048], V at col 1024)
// =====================================================================
__global__ __launch_bounds__(256) void pair_kernel(
    const float* __restrict__ UV, const float* __restrict__ b_i1,
    const float* __restrict__ W_i2, const float* __restrict__ b_i2,
    float* __restrict__ out)
{
    int p = blockIdx.x;
    int b = p / NPAIR_B, q = p % NPAIR_B;
    int i = q / (MAXN - 1), jj = q % (MAXN - 1);
    int j = jj + (jj >= i ? 1 : 0);
    const float* U = UV + (size_t)(b * MAXN + i) * (2 * NFB);
    const float* V = UV + (size_t)(b * MAXN + j) * (2 * NFB) + NFB;

    int tid = threadIdx.x, lane = tid & 31, wid = tid >> 5;
    int c = tid * 4;
    __shared__ float sred[16];

    float4 u  = *(const float4*)(U + c);
    float4 v  = *(const float4*)(V + c);
    float4 bi = *(const float4*)(b_i1 + c);
    float4 w0 = *(const float4*)(W_i2 + c);
    float4 w1 = *(const float4*)(W_i2 + NFB + c);

    float t0 = fmaxf(u.x + v.x + bi.x, 0.f);
    float t1 = fmaxf(u.y + v.y + bi.y, 0.f);
    float t2 = fmaxf(u.z + v.z + bi.z, 0.f);
    float t3 = fmaxf(u.w + v.w + bi.w, 0.f);
    float a0 = t0 * w0.x + t1 * w0.y + t2 * w0.z + t3 * w0.w;
    float a1 = t0 * w1.x + t1 * w1.y + t2 * w1.z + t3 * w1.w;
#pragma unroll
    for (int s = 16; s; s >>= 1) {
        a0 += __shfl_down_sync(0xffffffffu, a0, s);
        a1 += __shfl_down_sync(0xffffffffu, a1, s);
    }
    if (lane == 0) { sred[wid * 2] = a0; sred[wid * 2 + 1] = a1; }
    __syncthreads();
    if (tid < 2) {
        float s = 0.f;
#pragma unroll
        for (int w = 0; w < 8; ++w) s += sred[w * 2 + tid];
        out[p * 2 + tid] = s + b_i2[tid];
    }
}

// =====================================================================
// launch (multi-stream fork/join, graph-capturable)
// =====================================================================
extern "C" void kernel_launch(void* const* d_in, const int* in_sizes, int n_in,
                              void* d_out, int out_size)
{
    const float* features = (const float*)d_in[0];
    const float* boxes    = (const float*)d_in[1];
    const float* W_emb = (const float*)d_in[3];
    const float* b_emb = (const float*)d_in[4];
    const float* ln_g  = (const float*)d_in[5];
    const float* ln_b  = (const float*)d_in[6];
    const float* W_act = (const float*)d_in[7];
    const float* b_act = (const float*)d_in[8];
    const float* W_i1  = (const float*)d_in[9];
    const float* b_i1  = (const float*)d_in[10];
    const float* W_i2  = (const float*)d_in[11];
    const float* b_i2  = (const float*)d_in[12];
    float* out = (float*)d_out;

    void *ae, *be, *bu, *fh, *pp, *uvpp, *uvp;
    cudaGetSymbolAddress(&ae, g_Ae);  cudaGetSymbolAddress(&be, g_Be);
    cudaGetSymbolAddress(&bu, g_Bu);  cudaGetSymbolAddress(&fh, g_f);
    cudaGetSymbolAddress(&pp, g_part); cudaGetSymbolAddress(&uvpp, g_UVp);
    cudaGetSymbolAddress(&uvp, g_UV);

    static cudaStream_t s1 = nullptr, s2 = nullptr;
    static cudaEvent_t evFork = nullptr, evWemb = nullptr, evWi1 = nullptr;
    if (!s1) {
        cudaFuncSetAttribute(hmma_gemm, cudaFuncAttributeMaxDynamicSharedMemorySize, SMEM_DYN);
        cudaStreamCreateWithFlags(&s1, cudaStreamNonBlocking);
        cudaStreamCreateWithFlags(&s2, cudaStreamNonBlocking);
        cudaEventCreateWithFlags(&evFork, cudaEventDisableTiming);
        cudaEventCreateWithFlags(&evWemb, cudaEventDisableTiming);
        cudaEventCreateWithFlags(&evWi1,  cudaEventDisableTiming);
    }

    // ---- fork: weight conversions on side streams, roi-align on main
    cudaEventRecord(evFork, 0);
    cudaStreamWaitEvent(s1, evFork, 0);
    cudaStreamWaitEvent(s2, evFork, 0);

    conv_wemb<<<dim3(KPAD_E / 2048, NFB), 256, 0, s1>>>(W_emb, (__half*)be);
    cudaEventRecord(evWemb, s1);
    conv_wi1<<<2 * NFB, 128, 0, s2>>>(W_i1, (__half*)bu);
    cudaEventRecord(evWi1, s2);

    roi_align_kernel<<<dim3(D_CH / 32, R_TOT), 256>>>(features, boxes, (__half*)ae);

    // ---- join W_emb before embedding GEMM
    cudaStreamWaitEvent(0, evWemb, 0);

    // embedding GEMM: [208 x 26624] x [1024 x 26624]^T, split-K=32, N tile 256
    hmma_gemm<<<dim3(NFB / 256, 4, KSPLIT), 256, SMEM_DYN>>>(
        (const __half*)ae, (const __half*)be,
        KPAD_E, KT_E, (float*)pp, (long)R_TOT * NFB, NFB, R_TOT);

    // reduce + LN + ReLU + action head
    ln_act_kernel<<<R_TOT, 256>>>((const float*)pp, b_emb, ln_g, ln_b, W_act, b_act,
                                  (__half*)fh, out);

    // ---- join W_i1 before UV GEMM
    cudaStreamWaitEvent(0, evWi1, 0);

    // UV GEMM: [208 x 1024] x [2048 x 1024]^T, split-K=4 -> partials
    hmma_gemm<<<dim3(2 * NFB / 256, 4, KSPLIT_U), 256, SMEM_DYN>>>(
        (const __half*)fh, (const __half*)bu,
        KPAD_U, KT_U, (float*)uvpp, (long)R_TOT * 2 * NFB, 2 * NFB, R_TOT);
    uv_reduce<<<(R_TOT * 2 * NFB) / (256 * 4), 256>>>((const float*)uvpp, (float*)uvp);

    // pairwise combine + interaction head
    pair_kernel<<<NPAIR, 256>>>((const float*)uvp, b_i1, W_i2, b_i2, out + R_TOT * NA);
}